// round 1
// baseline (speedup 1.0000x reference)
#include <cuda_runtime.h>
#include <cuda_bf16.h>
#include <cstdint>

#define BATCH   4096
#define DIM     1024
#define NSAMP   32768
#define NSPLIT  8
#define NCHUNK  (NSAMP / NSPLIT)   // 4096 features per CTA
#define MBLK    128
#define NTILE   128
#define KTILE   64
#define TEMP_INV 20.0f
#define EXP_SCALE (20.0f * 1.4426950408889634f)  // (1/temp) * log2(e)

// ---- persistent device scratch (no runtime allocation allowed) ----
__device__ __nv_bfloat16 g_xb[BATCH * DIM];          // normalized inputs, bf16
__device__ float         g_partial[BATCH * NSPLIT];  // partial sum-exp per (row, nsplit)
__device__ float         g_tlogit[BATCH];            // target logit (already /temp)

// ---------------------------------------------------------------
// fast exp2 via FFMA polynomial (avoids MUFU bottleneck: 134M exps)
// input y = logit * log2e, |y| <= ~30.  rel err ~1e-7 (Cephes coeffs).
// ---------------------------------------------------------------
__device__ __forceinline__ float fast_exp2(float y) {
    int   n = __float2int_rn(y);
    float f = y - (float)n;                 // f in [-0.5, 0.5]
    float p = fmaf(1.535336188319500e-4f, f, 1.339887440266574e-3f);
    p = fmaf(p, f, 9.618437357674640e-3f);
    p = fmaf(p, f, 5.550332471162809e-2f);
    p = fmaf(p, f, 2.402264791363012e-1f);
    p = fmaf(p, f, 6.931472028550421e-1f);
    float m = fmaf(p, f, 1.0f);             // 2^f in [0.707, 1.414]
    return __int_as_float(__float_as_int(m) + (n << 23));
}

// ---------------------------------------------------------------
// Kernel 1: L2-normalize rows of inputs, write bf16
// ---------------------------------------------------------------
__global__ void knorm(const float* __restrict__ x) {
    int row = blockIdx.x;
    int t = threadIdx.x;  // 256 threads, 1 float4 each (1024 floats/row)
    const float4* xr = reinterpret_cast<const float4*>(x + (size_t)row * DIM);
    float4 v = xr[t];
    float ss = v.x * v.x + v.y * v.y + v.z * v.z + v.w * v.w;
    #pragma unroll
    for (int o = 16; o; o >>= 1) ss += __shfl_xor_sync(~0u, ss, o);
    __shared__ float sw[8];
    if ((t & 31) == 0) sw[t >> 5] = ss;
    __syncthreads();
    float tot = sw[0] + sw[1] + sw[2] + sw[3] + sw[4] + sw[5] + sw[6] + sw[7];
    float scale = rsqrtf(fmaxf(tot, 1e-24f));
    __nv_bfloat162* dst = reinterpret_cast<__nv_bfloat162*>(g_xb + (size_t)row * DIM + t * 4);
    dst[0] = __floats2bfloat162_rn(v.x * scale, v.y * scale);
    dst[1] = __floats2bfloat162_rn(v.z * scale, v.w * scale);
}

// ---------------------------------------------------------------
// ldmatrix / mma wrappers
// ---------------------------------------------------------------
__device__ __forceinline__ void ldsm_x4(uint32_t& r0, uint32_t& r1, uint32_t& r2, uint32_t& r3,
                                        uint32_t addr) {
    asm volatile("ldmatrix.sync.aligned.m8n8.x4.shared.b16 {%0,%1,%2,%3}, [%4];\n"
                 : "=r"(r0), "=r"(r1), "=r"(r2), "=r"(r3) : "r"(addr));
}
__device__ __forceinline__ void ldsm_x2(uint32_t& r0, uint32_t& r1, uint32_t addr) {
    asm volatile("ldmatrix.sync.aligned.m8n8.x2.shared.b16 {%0,%1}, [%2];\n"
                 : "=r"(r0), "=r"(r1) : "r"(addr));
}
__device__ __forceinline__ void mma_bf16(float& c0, float& c1, float& c2, float& c3,
                                         uint32_t a0, uint32_t a1, uint32_t a2, uint32_t a3,
                                         uint32_t b0, uint32_t b1) {
    asm volatile(
        "mma.sync.aligned.m16n8k16.row.col.f32.bf16.bf16.f32 "
        "{%0,%1,%2,%3}, {%4,%5,%6,%7}, {%8,%9}, {%0,%1,%2,%3};\n"
        : "+f"(c0), "+f"(c1), "+f"(c2), "+f"(c3)
        : "r"(a0), "r"(a1), "r"(a2), "r"(a3), "r"(b0), "r"(b1));
}

// ---------------------------------------------------------------
// Kernel 2: per-(M-block, N-split) partial logits + exp-sum + target pick
// grid(32, 8), 256 threads (8 warps as 2m x 4n; warp tile 64x32)
// ---------------------------------------------------------------
#define SLD 72   // smem leading dim (bf16 elems): 64 + 8 pad, conflict-free ldmatrix

__global__ __launch_bounds__(256, 2)
void kmain(const float* __restrict__ feats, const long long* __restrict__ ctgt) {
    const int mblk = blockIdx.x;          // 0..31
    const int nsp  = blockIdx.y;          // 0..7
    const int m0 = mblk * MBLK;
    const int nbase = nsp * NCHUNK;
    const int t = threadIdx.x;
    const int lane = t & 31, warp = t >> 5;
    const int wm = warp >> 2;             // 0..1 (64 rows each)
    const int wn = warp & 3;              // 0..3 (32 cols each)

    __shared__ __nv_bfloat16 sA[MBLK * SLD];
    __shared__ __nv_bfloat16 sB[NTILE * SLD];
    __shared__ float s_rowsum[4][MBLK];   // per n-warp slot -> deterministic combine
    __shared__ int   s_tgt[MBLK];

    if (t < MBLK) {
        s_tgt[t] = (int)ctgt[m0 + t];
        s_rowsum[0][t] = 0.f; s_rowsum[1][t] = 0.f;
        s_rowsum[2][t] = 0.f; s_rowsum[3][t] = 0.f;
    }

    // per-thread running exp-sums for its 8 fixed rows
    float accrow[8];
    #pragma unroll
    for (int i = 0; i < 8; i++) accrow[i] = 0.f;

    // precompute ldmatrix shared addresses (byte offsets)
    uint32_t sA_base = (uint32_t)__cvta_generic_to_shared(sA);
    uint32_t sB_base = (uint32_t)__cvta_generic_to_shared(sB);
    // A: lanes 0-15 -> rows, lanes 16-31 -> +8 cols
    uint32_t a_row = (uint32_t)(wm * 64 + (lane & 15));
    uint32_t a_coff = (uint32_t)((lane >> 4) * 8);
    // B: lanes 0-7 -> n rows @k, lanes 8-15 -> n rows @k+8 (x2 uses lanes 0-15)
    uint32_t b_row = (uint32_t)(wn * 32 + (lane & 7));
    uint32_t b_coff = (uint32_t)(((lane >> 3) & 1) * 8);

    for (int nt = 0; nt < NCHUNK / NTILE; nt++) {
        const int n0 = nbase + nt * NTILE;
        float c[4][4][4];
        #pragma unroll
        for (int i = 0; i < 4; i++)
            #pragma unroll
            for (int j = 0; j < 4; j++) {
                c[i][j][0] = 0.f; c[i][j][1] = 0.f; c[i][j][2] = 0.f; c[i][j][3] = 0.f;
            }

        for (int k0 = 0; k0 < DIM; k0 += KTILE) {
            __syncthreads();
            // ---- load A tile (bf16, 128x64) ----
            #pragma unroll
            for (int i = 0; i < 4; i++) {
                int idx = i * 256 + t;
                int r = idx >> 3, c8 = idx & 7;
                uint4 v = *reinterpret_cast<const uint4*>(
                    g_xb + (size_t)(m0 + r) * DIM + k0 + c8 * 8);
                *reinterpret_cast<uint4*>(sA + r * SLD + c8 * 8) = v;
            }
            // ---- load B tile (fp32 -> bf16, 128x64) ----
            #pragma unroll
            for (int i = 0; i < 8; i++) {
                int idx = i * 256 + t;
                int r = idx >> 4, c4 = idx & 15;
                float4 v = *reinterpret_cast<const float4*>(
                    feats + (size_t)(n0 + r) * DIM + k0 + c4 * 4);
                __nv_bfloat162* dst =
                    reinterpret_cast<__nv_bfloat162*>(sB + r * SLD + c4 * 4);
                dst[0] = __floats2bfloat162_rn(v.x, v.y);
                dst[1] = __floats2bfloat162_rn(v.z, v.w);
            }
            __syncthreads();

            // ---- MMA over 4 k-steps of 16 ----
            #pragma unroll
            for (int ks = 0; ks < 4; ks++) {
                uint32_t a[4][4], b[4][2];
                #pragma unroll
                for (int mt = 0; mt < 4; mt++) {
                    uint32_t addr = sA_base +
                        ((a_row + mt * 16) * SLD + (uint32_t)(ks * 16) + a_coff) * 2u;
                    ldsm_x4(a[mt][0], a[mt][1], a[mt][2], a[mt][3], addr);
                }
                #pragma unroll
                for (int ntl = 0; ntl < 4; ntl++) {
                    uint32_t addr = sB_base +
                        ((b_row + ntl * 8) * SLD + (uint32_t)(ks * 16) + b_coff) * 2u;
                    ldsm_x2(b[ntl][0], b[ntl][1], addr);
                }
                #pragma unroll
                for (int mt = 0; mt < 4; mt++)
                    #pragma unroll
                    for (int ntl = 0; ntl < 4; ntl++)
                        mma_bf16(c[mt][ntl][0], c[mt][ntl][1], c[mt][ntl][2], c[mt][ntl][3],
                                 a[mt][0], a[mt][1], a[mt][2], a[mt][3],
                                 b[ntl][0], b[ntl][1]);
            }
        }

        // ---- epilogue: exp-sum directly from register fragments ----
        #pragma unroll
        for (int mt = 0; mt < 4; mt++) {
            #pragma unroll
            for (int j2 = 0; j2 < 2; j2++) {
                int rloc = wm * 64 + mt * 16 + (lane >> 2) + j2 * 8;
                int tg = s_tgt[rloc];
                float rs = 0.f;
                #pragma unroll
                for (int ntl = 0; ntl < 4; ntl++) {
                    #pragma unroll
                    for (int jc = 0; jc < 2; jc++) {
                        float v = c[mt][ntl][j2 * 2 + jc];
                        int col = n0 + wn * 32 + ntl * 8 + (lane & 3) * 2 + jc;
                        if (col == tg) g_tlogit[m0 + rloc] = v * TEMP_INV;
                        rs += fast_exp2(v * EXP_SCALE);
                    }
                }
                accrow[mt * 2 + j2] += rs;
            }
        }
    }

    // ---- deterministic row-sum combine ----
    #pragma unroll
    for (int i = 0; i < 8; i++) {
        float v = accrow[i];
        v += __shfl_xor_sync(~0u, v, 1);
        v += __shfl_xor_sync(~0u, v, 2);
        if ((lane & 3) == 0) {
            int mt = i >> 1, j2 = i & 1;
            int rloc = wm * 64 + mt * 16 + (lane >> 2) + j2 * 8;
            s_rowsum[wn][rloc] = v;   // unique writer per (wn, rloc)
        }
    }
    __syncthreads();
    if (t < MBLK) {
        float s = s_rowsum[0][t] + s_rowsum[1][t] + s_rowsum[2][t] + s_rowsum[3][t];
        g_partial[(size_t)(m0 + t) * NSPLIT + nsp] = s;
    }
}

// ---------------------------------------------------------------
// Kernel 3: combine partials, NLL, mean  (single CTA)
// ---------------------------------------------------------------
__global__ void kfinal(float* __restrict__ out) {
    int t = threadIdx.x;  // 512
    float acc = 0.f;
    for (int r = t; r < BATCH; r += 512) {
        float s = 0.f;
        #pragma unroll
        for (int i = 0; i < NSPLIT; i++) s += g_partial[(size_t)r * NSPLIT + i];
        acc += logf(s) - g_tlogit[r];
    }
    #pragma unroll
    for (int o = 16; o; o >>= 1) acc += __shfl_xor_sync(~0u, acc, o);
    __shared__ float sw[16];
    if ((t & 31) == 0) sw[t >> 5] = acc;
    __syncthreads();
    if (t < 16) {
        float v = sw[t];
        #pragma unroll
        for (int o = 8; o; o >>= 1) v += __shfl_xor_sync(0xffff, v, o);
        if (t == 0) out[0] = v * (1.0f / BATCH);
    }
}

// ---------------------------------------------------------------
extern "C" void kernel_launch(void* const* d_in, const int* in_sizes, int n_in,
                              void* d_out, int out_size) {
    const float*     inputs = (const float*)d_in[0];
    // d_in[1] = targets (unused by reference computation)
    const long long* ctgt   = (const long long*)d_in[2];
    const float*     feats  = (const float*)d_in[3];
    float* out = (float*)d_out;

    knorm<<<BATCH, 256>>>(inputs);
    dim3 grid(BATCH / MBLK, NSPLIT);   // (32, 8): consecutive bids share N-split -> L2 reuse
    kmain<<<grid, 256>>>(feats, ctgt);
    kfinal<<<1, 512>>>(out);
}

// round 4
// speedup vs baseline: 1.0936x; 1.0936x over previous
#include <cuda_runtime.h>
#include <cuda_fp16.h>
#include <cstdint>

#define BATCH   4096
#define DIM     1024
#define NSAMP   32768
#define MT      128                  // CTA M tile
#define NT      256                  // CTA N tile
#define KC      64                   // K chunk (fp16 elems) = 128B row
#define NKC     (DIM / KC)           // 16
#define MTILES  (BATCH / MT)         // 32
#define NTILES  (NSAMP / NT)         // 128
#define SLD     72                   // smem leading dim (fp16): 64 + 8 pad
#define ASTG    (MT * SLD * 2)       // 18432 B
#define BSTG    (NT * SLD * 2)       // 36864 B
#define STG     (ASTG + BSTG)        // 55296 B
#define SMEM_DYN (3 * STG)           // 165888 B
#define TEMP_INV 20.0f
#define EXP_SCALE (20.0f * 1.4426950408889634f)

// ---- persistent device scratch ----
__device__ __align__(16) __half g_xh[(size_t)BATCH * DIM];   // normalized inputs fp16
__device__ __align__(16) __half g_fh[(size_t)NSAMP * DIM];   // features fp16
__device__ float g_partial[(size_t)BATCH * NTILES];
__device__ float g_tlogit[BATCH];

// =============================== helpers ===============================
__device__ __forceinline__ uint32_t smem_u32(const void* p) {
    return (uint32_t)__cvta_generic_to_shared(p);
}
__device__ __forceinline__ void cp16(uint32_t dst, const void* src) {
    asm volatile("cp.async.cg.shared.global [%0], [%1], 16;" :: "r"(dst), "l"(src));
}
#define CP_COMMIT() asm volatile("cp.async.commit_group;" ::: "memory")
#define CP_WAIT(N)  asm volatile("cp.async.wait_group " #N ";" ::: "memory")

__device__ __forceinline__ uint32_t h2u(__half2 v) {
    // 4-byte -> 4-byte reinterpret (alignment-safe)
    return *reinterpret_cast<uint32_t*>(&v);
}

__device__ __forceinline__ void ldsm_x4(uint32_t& r0, uint32_t& r1, uint32_t& r2, uint32_t& r3,
                                        uint32_t addr) {
    asm volatile("ldmatrix.sync.aligned.m8n8.x4.shared.b16 {%0,%1,%2,%3}, [%4];"
                 : "=r"(r0), "=r"(r1), "=r"(r2), "=r"(r3) : "r"(addr));
}
__device__ __forceinline__ void mma_f16(float& c0, float& c1, float& c2, float& c3,
                                        uint32_t a0, uint32_t a1, uint32_t a2, uint32_t a3,
                                        uint32_t b0, uint32_t b1) {
    asm volatile(
        "mma.sync.aligned.m16n8k16.row.col.f32.f16.f16.f32 "
        "{%0,%1,%2,%3}, {%4,%5,%6,%7}, {%8,%9}, {%0,%1,%2,%3};"
        : "+f"(c0), "+f"(c1), "+f"(c2), "+f"(c3)
        : "r"(a0), "r"(a1), "r"(a2), "r"(a3), "r"(b0), "r"(b1));
}

// ===================== Kernel 1: normalize inputs -> fp16 =====================
__global__ void knorm(const float* __restrict__ x) {
    int row = blockIdx.x;
    int t = threadIdx.x;  // 256 threads, 4 floats each
    const float4* xr = reinterpret_cast<const float4*>(x + (size_t)row * DIM);
    float4 v = xr[t];
    float ss = v.x * v.x + v.y * v.y + v.z * v.z + v.w * v.w;
    #pragma unroll
    for (int o = 16; o; o >>= 1) ss += __shfl_xor_sync(~0u, ss, o);
    __shared__ float sw[8];
    if ((t & 31) == 0) sw[t >> 5] = ss;
    __syncthreads();
    float tot = sw[0] + sw[1] + sw[2] + sw[3] + sw[4] + sw[5] + sw[6] + sw[7];
    float sc = rsqrtf(fmaxf(tot, 1e-24f));
    uint2 o;
    o.x = h2u(__floats2half2_rn(v.x * sc, v.y * sc));
    o.y = h2u(__floats2half2_rn(v.z * sc, v.w * sc));
    *reinterpret_cast<uint2*>(g_xh + (size_t)row * DIM + t * 4) = o;
}

// ===================== Kernel 1b: features fp32 -> fp16 =====================
__global__ void kconv(const float* __restrict__ f) {
    size_t i = ((size_t)blockIdx.x * 256 + threadIdx.x) * 4;   // 4 elems/thread
    float4 a = *reinterpret_cast<const float4*>(f + i);
    uint2 o;
    o.x = h2u(__floats2half2_rn(a.x, a.y));
    o.y = h2u(__floats2half2_rn(a.z, a.w));
    *reinterpret_cast<uint2*>(g_fh + i) = o;                   // 8B-aligned store
}

// ===================== Kernel 1c: target logits (fp16 dot) =====================
__global__ void ktgt(const long long* __restrict__ ctgt) {
    int row = blockIdx.x;
    int t = threadIdx.x;  // 128 threads
    long long tg64 = ctgt[row];
    int tg = (int)(tg64 < 0 ? 0 : (tg64 >= NSAMP ? NSAMP - 1 : tg64));
    const __half2* x = reinterpret_cast<const __half2*>(g_xh + (size_t)row * DIM);
    const __half2* f = reinterpret_cast<const __half2*>(g_fh + (size_t)tg * DIM);
    float s = 0.f;
    #pragma unroll
    for (int i = 0; i < 4; i++) {
        float2 fa = __half22float2(x[t * 4 + i]);
        float2 fb = __half22float2(f[t * 4 + i]);
        s = fmaf(fa.x, fb.x, s);
        s = fmaf(fa.y, fb.y, s);
    }
    #pragma unroll
    for (int o = 16; o; o >>= 1) s += __shfl_xor_sync(~0u, s, o);
    __shared__ float sw[4];
    if ((t & 31) == 0) sw[t >> 5] = s;
    __syncthreads();
    if (t == 0) g_tlogit[row] = (sw[0] + sw[1] + sw[2] + sw[3]) * TEMP_INV;
}

// ===================== Kernel 2: HMMA main, 3-stage cp.async =====================
__device__ __forceinline__ void load_chunk(int m0, int n0, int c,
                                           uint32_t stA, uint32_t stB, int t) {
    const int k0 = c * KC;
    const __half* As = g_xh + (size_t)m0 * DIM + k0;
    const __half* Bs = g_fh + (size_t)n0 * DIM + k0;
    #pragma unroll
    for (int it = 0; it < 2; it++) {              // A: 128 rows x 128B
        int idx = it * 512 + t;
        int r = idx >> 3, cc = idx & 7;
        cp16(stA + (uint32_t)(r * (SLD * 2) + cc * 16), As + (size_t)r * DIM + cc * 8);
    }
    #pragma unroll
    for (int it = 0; it < 4; it++) {              // B: 256 rows x 128B
        int idx = it * 512 + t;
        int r = idx >> 3, cc = idx & 7;
        cp16(stB + (uint32_t)(r * (SLD * 2) + cc * 16), Bs + (size_t)r * DIM + cc * 8);
    }
    CP_COMMIT();
}

__global__ __launch_bounds__(512, 1)
void kmain() {
    extern __shared__ __align__(16) char dyn[];
    __shared__ float s_rowsum[4][MT];

    const int t = threadIdx.x;
    const int lane = t & 31, warp = t >> 5;
    const int wm = warp & 3;                 // 0..3, rows wm*32
    const int wn = warp >> 2;                // 0..3, cols wn*64
    const int m0 = blockIdx.x * MT;
    const int nti = blockIdx.y;
    const int n0 = nti * NT;

    const uint32_t base = smem_u32(dyn);

    // ldsm lane addressing (elements)
    const uint32_t a_row  = (uint32_t)(wm * 32 + (lane & 15));
    const uint32_t a_coff = (uint32_t)((lane >> 4) * 8);
    const uint32_t b_row  = (uint32_t)(wn * 64 + ((lane >> 4) * 8) + (lane & 7));
    const uint32_t b_coff = (uint32_t)(((lane >> 3) & 1) * 8);

    float c[2][8][4];
    #pragma unroll
    for (int i = 0; i < 2; i++)
        #pragma unroll
        for (int j = 0; j < 8; j++)
            #pragma unroll
            for (int q = 0; q < 4; q++) c[i][j][q] = 0.f;

    // prologue: chunks 0,1 -> stages 0,1
    load_chunk(m0, n0, 0, base,       base + ASTG,       t);
    load_chunk(m0, n0, 1, base + STG, base + STG + ASTG, t);

    #pragma unroll 1
    for (int i = 0; i < NKC; i++) {
        if (i < NKC - 2) { CP_WAIT(1); } else { CP_WAIT(0); }
        __syncthreads();
        if (i + 2 < NKC) {
            const int sj = (i + 2) % 3;
            load_chunk(m0, n0, i + 2, base + sj * STG, base + sj * STG + ASTG, t);
        }
        const uint32_t sA = base + (uint32_t)(i % 3) * STG;
        const uint32_t sB = sA + ASTG;
        #pragma unroll
        for (int ks = 0; ks < 4; ks++) {
            uint32_t a[2][4], b[4][4];
            #pragma unroll
            for (int mt = 0; mt < 2; mt++) {
                uint32_t addr = sA + ((a_row + mt * 16) * SLD + ks * 16 + a_coff) * 2u;
                ldsm_x4(a[mt][0], a[mt][1], a[mt][2], a[mt][3], addr);
            }
            #pragma unroll
            for (int np = 0; np < 4; np++) {
                uint32_t addr = sB + ((b_row + np * 16) * SLD + ks * 16 + b_coff) * 2u;
                ldsm_x4(b[np][0], b[np][1], b[np][2], b[np][3], addr);
            }
            #pragma unroll
            for (int mt = 0; mt < 2; mt++)
                #pragma unroll
                for (int np = 0; np < 4; np++) {
                    mma_f16(c[mt][2*np][0], c[mt][2*np][1], c[mt][2*np][2], c[mt][2*np][3],
                            a[mt][0], a[mt][1], a[mt][2], a[mt][3], b[np][0], b[np][1]);
                    mma_f16(c[mt][2*np+1][0], c[mt][2*np+1][1], c[mt][2*np+1][2], c[mt][2*np+1][3],
                            a[mt][0], a[mt][1], a[mt][2], a[mt][3], b[np][2], b[np][3]);
                }
        }
    }

    // ---- epilogue: exp-sum from register fragments ----
    float accrow[4] = {0.f, 0.f, 0.f, 0.f};   // [mt][half]
    #pragma unroll
    for (int mt = 0; mt < 2; mt++)
        #pragma unroll
        for (int h = 0; h < 2; h++) {
            float rs = 0.f;
            #pragma unroll
            for (int ntl = 0; ntl < 8; ntl++)
                #pragma unroll
                for (int jc = 0; jc < 2; jc++) {
                    float v = c[mt][ntl][h * 2 + jc];
                    float e;
                    asm("ex2.approx.f32 %0, %1;" : "=f"(e) : "f"(v * EXP_SCALE));
                    rs += e;
                }
            accrow[mt * 2 + h] = rs;
        }
    #pragma unroll
    for (int i = 0; i < 4; i++) {
        float v = accrow[i];
        v += __shfl_xor_sync(~0u, v, 1);
        v += __shfl_xor_sync(~0u, v, 2);
        if ((lane & 3) == 0) {
            int row = wm * 32 + (i >> 1) * 16 + (lane >> 2) + (i & 1) * 8;
            s_rowsum[wn][row] = v;
        }
    }
    __syncthreads();
    if (t < MT)
        g_partial[(size_t)(m0 + t) * NTILES + nti] =
            (s_rowsum[0][t] + s_rowsum[1][t]) + (s_rowsum[2][t] + s_rowsum[3][t]);
}

// ===================== Kernel 3: final reduce =====================
__global__ void kfinal(float* __restrict__ out) {
    int t = threadIdx.x;  // 512
    float acc = 0.f;
    for (int r = t; r < BATCH; r += 512) {
        const float* p = g_partial + (size_t)r * NTILES;
        float s = 0.f;
        #pragma unroll 8
        for (int i = 0; i < NTILES; i++) s += p[i];
        acc += logf(s) - g_tlogit[r];
    }
    #pragma unroll
    for (int o = 16; o; o >>= 1) acc += __shfl_xor_sync(~0u, acc, o);
    __shared__ float sw[16];
    if ((t & 31) == 0) sw[t >> 5] = acc;
    __syncthreads();
    if (t < 16) {
        float v = sw[t];
        #pragma unroll
        for (int o = 8; o; o >>= 1) v += __shfl_xor_sync(0xffff, v, o);
        if (t == 0) out[0] = v * (1.0f / BATCH);
    }
}

// ===========================================================================
extern "C" void kernel_launch(void* const* d_in, const int* in_sizes, int n_in,
                              void* d_out, int out_size) {
    const float*     inputs = (const float*)d_in[0];
    const long long* ctgt   = (const long long*)d_in[2];
    const float*     feats  = (const float*)d_in[3];
    float* out = (float*)d_out;

    cudaFuncSetAttribute(kmain, cudaFuncAttributeMaxDynamicSharedMemorySize, SMEM_DYN);

    knorm<<<BATCH, 256>>>(inputs);
    kconv<<<(NSAMP * DIM / 4) / 256, 256>>>(feats);   // 32768 blocks, 4 elems/thread
    ktgt<<<BATCH, 128>>>(ctgt);
    dim3 grid(MTILES, NTILES);   // x = m (fast) -> 32 CTAs share each B tile
    kmain<<<grid, 512, SMEM_DYN>>>();
    kfinal<<<1, 512>>>(out);
}

// round 5
// speedup vs baseline: 1.5725x; 1.4380x over previous
#include <cuda_runtime.h>
#include <cuda_fp16.h>
#include <cstdint>

#define BATCH   4096
#define DIM     1024
#define NSAMP   32768
#define MT      128                  // CTA M tile
#define NT      128                  // CTA N tile
#define KC      64                   // K chunk (fp16 elems) = 128B row
#define NKC     (DIM / KC)           // 16
#define MTILES  (BATCH / MT)         // 32
#define NTILES  (NSAMP / NT)         // 256
#define SLD     72                   // smem leading dim (fp16): 64 + 8 pad
#define ASTG    (MT * SLD * 2)       // 18432 B
#define BSTG    (NT * SLD * 2)       // 18432 B
#define STG     (ASTG + BSTG)        // 36864 B
#define SMEM_DYN (3 * STG)           // 110592 B
#define TEMP_INV 20.0f
#define EXP_SCALE (20.0f * 1.4426950408889634f)

// ---- persistent device scratch ----
__device__ __align__(16) __half g_xh[(size_t)BATCH * DIM];   // normalized inputs fp16
__device__ __align__(16) __half g_fh[(size_t)NSAMP * DIM];   // features fp16
__device__ float g_partial[(size_t)BATCH * NTILES];
__device__ float g_tlogit[BATCH];
__device__ float g_rnorm[BATCH];
__device__ float g_bsum[32];

// =============================== helpers ===============================
__device__ __forceinline__ uint32_t smem_u32(const void* p) {
    return (uint32_t)__cvta_generic_to_shared(p);
}
__device__ __forceinline__ void cp16(uint32_t dst, const void* src) {
    asm volatile("cp.async.cg.shared.global [%0], [%1], 16;" :: "r"(dst), "l"(src));
}
#define CP_COMMIT() asm volatile("cp.async.commit_group;" ::: "memory")
#define CP_WAIT(N)  asm volatile("cp.async.wait_group " #N ";" ::: "memory")

__device__ __forceinline__ uint32_t h2u(__half2 v) {
    return *reinterpret_cast<uint32_t*>(&v);
}
__device__ __forceinline__ void ldsm_x4(uint32_t& r0, uint32_t& r1, uint32_t& r2, uint32_t& r3,
                                        uint32_t addr) {
    asm volatile("ldmatrix.sync.aligned.m8n8.x4.shared.b16 {%0,%1,%2,%3}, [%4];"
                 : "=r"(r0), "=r"(r1), "=r"(r2), "=r"(r3) : "r"(addr));
}
__device__ __forceinline__ void mma_f16(float& c0, float& c1, float& c2, float& c3,
                                        uint32_t a0, uint32_t a1, uint32_t a2, uint32_t a3,
                                        uint32_t b0, uint32_t b1) {
    asm volatile(
        "mma.sync.aligned.m16n8k16.row.col.f32.f16.f16.f32 "
        "{%0,%1,%2,%3}, {%4,%5,%6,%7}, {%8,%9}, {%0,%1,%2,%3};"
        : "+f"(c0), "+f"(c1), "+f"(c2), "+f"(c3)
        : "r"(a0), "r"(a1), "r"(a2), "r"(a3), "r"(b0), "r"(b1));
}

// ===================== Kernel 1: normalize inputs -> fp16 (+store 1/norm) ===
__global__ void knorm(const float* __restrict__ x) {
    int row = blockIdx.x;
    int t = threadIdx.x;  // 256 threads, 4 floats each
    const float4* xr = reinterpret_cast<const float4*>(x + (size_t)row * DIM);
    float4 v = xr[t];
    float ss = v.x * v.x + v.y * v.y + v.z * v.z + v.w * v.w;
    #pragma unroll
    for (int o = 16; o; o >>= 1) ss += __shfl_xor_sync(~0u, ss, o);
    __shared__ float sw[8];
    if ((t & 31) == 0) sw[t >> 5] = ss;
    __syncthreads();
    float tot = sw[0] + sw[1] + sw[2] + sw[3] + sw[4] + sw[5] + sw[6] + sw[7];
    float sc = rsqrtf(fmaxf(tot, 1e-24f));
    if (t == 0) g_rnorm[row] = sc;
    uint2 o;
    o.x = h2u(__floats2half2_rn(v.x * sc, v.y * sc));
    o.y = h2u(__floats2half2_rn(v.z * sc, v.w * sc));
    *reinterpret_cast<uint2*>(g_xh + (size_t)row * DIM + t * 4) = o;
}

// ===================== Kernel 1b: features fp32 -> fp16 =====================
__global__ void kconv(const float* __restrict__ f) {
    size_t i = ((size_t)blockIdx.x * 256 + threadIdx.x) * 4;
    float4 a = *reinterpret_cast<const float4*>(f + i);
    uint2 o;
    o.x = h2u(__floats2half2_rn(a.x, a.y));
    o.y = h2u(__floats2half2_rn(a.z, a.w));
    *reinterpret_cast<uint2*>(g_fh + i) = o;
}

// ===================== Kernel 1c: target logits (full fp32) =====================
__global__ void ktgt(const float* __restrict__ x, const float* __restrict__ feats,
                     const long long* __restrict__ ctgt) {
    int row = blockIdx.x;
    int t = threadIdx.x;  // 256 threads, 4 floats each
    long long tg64 = ctgt[row];
    int tg = (int)(tg64 < 0 ? 0 : (tg64 >= NSAMP ? NSAMP - 1 : tg64));
    float4 a = reinterpret_cast<const float4*>(x + (size_t)row * DIM)[t];
    float4 b = reinterpret_cast<const float4*>(feats + (size_t)tg * DIM)[t];
    float s = a.x * b.x + a.y * b.y + a.z * b.z + a.w * b.w;
    #pragma unroll
    for (int o = 16; o; o >>= 1) s += __shfl_xor_sync(~0u, s, o);
    __shared__ float sw[8];
    if ((t & 31) == 0) sw[t >> 5] = s;
    __syncthreads();
    if (t == 0) {
        float tot = sw[0] + sw[1] + sw[2] + sw[3] + sw[4] + sw[5] + sw[6] + sw[7];
        g_tlogit[row] = tot * g_rnorm[row] * TEMP_INV;
    }
}

// ===================== Kernel 2: HMMA main, 3-stage, 2 CTAs/SM ==============
__device__ __forceinline__ void load_chunk(int m0, int n0, int c,
                                           uint32_t stA, uint32_t stB, int t) {
    const int k0 = c * KC;
    const __half* As = g_xh + (size_t)m0 * DIM + k0;
    const __half* Bs = g_fh + (size_t)n0 * DIM + k0;
    #pragma unroll
    for (int it = 0; it < 4; it++) {              // A: 128 rows x 128B
        int idx = it * 256 + t;
        int r = idx >> 3, cc = idx & 7;
        cp16(stA + (uint32_t)(r * (SLD * 2) + cc * 16), As + (size_t)r * DIM + cc * 8);
    }
    #pragma unroll
    for (int it = 0; it < 4; it++) {              // B: 128 rows x 128B
        int idx = it * 256 + t;
        int r = idx >> 3, cc = idx & 7;
        cp16(stB + (uint32_t)(r * (SLD * 2) + cc * 16), Bs + (size_t)r * DIM + cc * 8);
    }
    CP_COMMIT();
}

__global__ __launch_bounds__(256, 2)
void kmain() {
    extern __shared__ __align__(16) char dyn[];
    __shared__ float s_rowsum[2][MT];

    const int t = threadIdx.x;
    const int lane = t & 31, warp = t >> 5;
    const int wm = warp & 3;                 // 0..3, rows wm*32
    const int wn = warp >> 2;                // 0..1, cols wn*64
    const int m0 = blockIdx.x * MT;
    const int nti = blockIdx.y;
    const int n0 = nti * NT;

    const uint32_t base = smem_u32(dyn);

    const uint32_t a_row  = (uint32_t)(wm * 32 + (lane & 15));
    const uint32_t a_coff = (uint32_t)((lane >> 4) * 8);
    const uint32_t b_row  = (uint32_t)(wn * 64 + ((lane >> 4) * 8) + (lane & 7));
    const uint32_t b_coff = (uint32_t)(((lane >> 3) & 1) * 8);

    float c[2][8][4];
    #pragma unroll
    for (int i = 0; i < 2; i++)
        #pragma unroll
        for (int j = 0; j < 8; j++)
            #pragma unroll
            for (int q = 0; q < 4; q++) c[i][j][q] = 0.f;

    load_chunk(m0, n0, 0, base,       base + ASTG,       t);
    load_chunk(m0, n0, 1, base + STG, base + STG + ASTG, t);

    #pragma unroll 1
    for (int i = 0; i < NKC; i++) {
        if (i < NKC - 2) { CP_WAIT(1); } else { CP_WAIT(0); }
        __syncthreads();
        if (i + 2 < NKC) {
            const int sj = (i + 2) % 3;
            load_chunk(m0, n0, i + 2, base + sj * STG, base + sj * STG + ASTG, t);
        }
        const uint32_t sA = base + (uint32_t)(i % 3) * STG;
        const uint32_t sB = sA + ASTG;
        #pragma unroll
        for (int ks = 0; ks < 4; ks++) {
            uint32_t a[2][4], b[4][4];
            #pragma unroll
            for (int mt = 0; mt < 2; mt++) {
                uint32_t addr = sA + ((a_row + mt * 16) * SLD + ks * 16 + a_coff) * 2u;
                ldsm_x4(a[mt][0], a[mt][1], a[mt][2], a[mt][3], addr);
            }
            #pragma unroll
            for (int np = 0; np < 4; np++) {
                uint32_t addr = sB + ((b_row + np * 16) * SLD + ks * 16 + b_coff) * 2u;
                ldsm_x4(b[np][0], b[np][1], b[np][2], b[np][3], addr);
            }
            #pragma unroll
            for (int mt = 0; mt < 2; mt++)
                #pragma unroll
                for (int np = 0; np < 4; np++) {
                    mma_f16(c[mt][2*np][0], c[mt][2*np][1], c[mt][2*np][2], c[mt][2*np][3],
                            a[mt][0], a[mt][1], a[mt][2], a[mt][3], b[np][0], b[np][1]);
                    mma_f16(c[mt][2*np+1][0], c[mt][2*np+1][1], c[mt][2*np+1][2], c[mt][2*np+1][3],
                            a[mt][0], a[mt][1], a[mt][2], a[mt][3], b[np][2], b[np][3]);
                }
        }
    }

    // ---- epilogue: exp-sum from register fragments ----
    float accrow[4];
    #pragma unroll
    for (int mt = 0; mt < 2; mt++)
        #pragma unroll
        for (int h = 0; h < 2; h++) {
            float rs = 0.f;
            #pragma unroll
            for (int ntl = 0; ntl < 8; ntl++)
                #pragma unroll
                for (int jc = 0; jc < 2; jc++) {
                    float v = c[mt][ntl][h * 2 + jc];
                    float e;
                    asm("ex2.approx.f32 %0, %1;" : "=f"(e) : "f"(v * EXP_SCALE));
                    rs += e;
                }
            accrow[mt * 2 + h] = rs;
        }
    #pragma unroll
    for (int i = 0; i < 4; i++) {
        float v = accrow[i];
        v += __shfl_xor_sync(~0u, v, 1);
        v += __shfl_xor_sync(~0u, v, 2);
        if ((lane & 3) == 0) {
            int row = wm * 32 + (i >> 1) * 16 + (lane >> 2) + (i & 1) * 8;
            s_rowsum[wn][row] = v;
        }
    }
    __syncthreads();
    if (t < MT)
        g_partial[(size_t)(m0 + t) * NTILES + nti] = s_rowsum[0][t] + s_rowsum[1][t];
}

// ===================== Kernel 3: final reduce (2-stage, deterministic) ======
__global__ void kfin1() {          // grid 32, block 256
    int b = blockIdx.x, t = threadIdx.x, w = t >> 5, lane = t & 31;
    float acc = 0.f;
    for (int r0 = w; r0 < 128; r0 += 8) {
        int row = b * 128 + r0;
        const float* p = g_partial + (size_t)row * NTILES;
        float s = 0.f;
        #pragma unroll 4
        for (int i = lane; i < NTILES; i += 32) s += p[i];
        #pragma unroll
        for (int o = 16; o; o >>= 1) s += __shfl_xor_sync(~0u, s, o);
        if (lane == 0) acc += logf(s) - g_tlogit[row];
    }
    __shared__ float sw[8];
    if (lane == 0) sw[w] = acc;
    __syncthreads();
    if (t == 0) {
        float v = 0.f;
        #pragma unroll
        for (int i = 0; i < 8; i++) v += sw[i];
        g_bsum[b] = v;
    }
}
__global__ void kfin2(float* __restrict__ out) {
    int t = threadIdx.x;  // 32
    float v = g_bsum[t];
    #pragma unroll
    for (int o = 16; o; o >>= 1) v += __shfl_xor_sync(~0u, v, o);
    if (t == 0) out[0] = v * (1.0f / BATCH);
}

// ===========================================================================
extern "C" void kernel_launch(void* const* d_in, const int* in_sizes, int n_in,
                              void* d_out, int out_size) {
    const float*     inputs = (const float*)d_in[0];
    const long long* ctgt   = (const long long*)d_in[2];
    const float*     feats  = (const float*)d_in[3];
    float* out = (float*)d_out;

    cudaFuncSetAttribute(kmain, cudaFuncAttributeMaxDynamicSharedMemorySize, SMEM_DYN);

    knorm<<<BATCH, 256>>>(inputs);
    kconv<<<(NSAMP * DIM / 4) / 256, 256>>>(feats);
    ktgt<<<BATCH, 256>>>(inputs, feats, ctgt);
    dim3 grid(MTILES, NTILES);   // x = m (fast): CTAs sharing a B tile run together
    kmain<<<grid, 256, SMEM_DYN>>>();
    kfin1<<<32, 256>>>();
    kfin2<<<1, 32>>>(out);
}

// round 6
// speedup vs baseline: 1.6984x; 1.0801x over previous
#include <cuda_runtime.h>
#include <cuda_fp16.h>
#include <cstdint>

#define BATCH   4096
#define DIM     1024
#define NSAMP   32768
#define MT      128                  // CTA M tile
#define NT      128                  // CTA N tile
#define KC      64                   // K chunk (fp16 elems) = 128B row
#define NKC     (DIM / KC)           // 16
#define MTILES  (BATCH / MT)         // 32
#define NTILES  (NSAMP / NT)         // 256
#define SLD     72                   // smem leading dim (fp16): 64 + 8 pad
#define ASTG    (MT * SLD * 2)       // 18432 B
#define BSTG    (NT * SLD * 2)       // 18432 B
#define STG     (ASTG + BSTG)        // 36864 B
#define SMEM_DYN (3 * STG)           // 110592 B
#define TEMP_INV 20.0f
#define EXP_SCALE (20.0f * 1.4426950408889634f)

// ---- persistent device scratch ----
__device__ __align__(16) __half g_xh[(size_t)BATCH * DIM];   // normalized inputs fp16
__device__ __align__(16) __half g_fh[(size_t)NSAMP * DIM];   // features fp16
__device__ float g_partial[(size_t)BATCH * NTILES];
__device__ float g_tlogit[BATCH];
__device__ float g_rnorm[BATCH];
__device__ float g_bsum[32];

// =============================== helpers ===============================
__device__ __forceinline__ uint32_t smem_u32(const void* p) {
    return (uint32_t)__cvta_generic_to_shared(p);
}
__device__ __forceinline__ void cp16(uint32_t dst, const void* src) {
    asm volatile("cp.async.cg.shared.global [%0], [%1], 16;" :: "r"(dst), "l"(src));
}
#define CP_COMMIT() asm volatile("cp.async.commit_group;" ::: "memory")
#define CP_WAIT(N)  asm volatile("cp.async.wait_group " #N ";" ::: "memory")

__device__ __forceinline__ uint32_t h2u(__half2 v) {
    return *reinterpret_cast<uint32_t*>(&v);
}
__device__ __forceinline__ void ldsm_x4(uint32_t& r0, uint32_t& r1, uint32_t& r2, uint32_t& r3,
                                        uint32_t addr) {
    asm volatile("ldmatrix.sync.aligned.m8n8.x4.shared.b16 {%0,%1,%2,%3}, [%4];"
                 : "=r"(r0), "=r"(r1), "=r"(r2), "=r"(r3) : "r"(addr));
}
__device__ __forceinline__ void mma_f16(float& c0, float& c1, float& c2, float& c3,
                                        uint32_t a0, uint32_t a1, uint32_t a2, uint32_t a3,
                                        uint32_t b0, uint32_t b1) {
    asm volatile(
        "mma.sync.aligned.m16n8k16.row.col.f32.f16.f16.f32 "
        "{%0,%1,%2,%3}, {%4,%5,%6,%7}, {%8,%9}, {%0,%1,%2,%3};"
        : "+f"(c0), "+f"(c1), "+f"(c2), "+f"(c3)
        : "r"(a0), "r"(a1), "r"(a2), "r"(a3), "r"(b0), "r"(b1));
}

// ===================== Kernel 1: normalize inputs -> fp16 (+store 1/norm) ===
__global__ void knorm(const float* __restrict__ x) {
    int row = blockIdx.x;
    int t = threadIdx.x;  // 256 threads, 4 floats each
    const float4* xr = reinterpret_cast<const float4*>(x + (size_t)row * DIM);
    float4 v = xr[t];
    float ss = v.x * v.x + v.y * v.y + v.z * v.z + v.w * v.w;
    #pragma unroll
    for (int o = 16; o; o >>= 1) ss += __shfl_xor_sync(~0u, ss, o);
    __shared__ float sw[8];
    if ((t & 31) == 0) sw[t >> 5] = ss;
    __syncthreads();
    float tot = sw[0] + sw[1] + sw[2] + sw[3] + sw[4] + sw[5] + sw[6] + sw[7];
    float sc = rsqrtf(fmaxf(tot, 1e-24f));
    if (t == 0) g_rnorm[row] = sc;
    uint2 o;
    o.x = h2u(__floats2half2_rn(v.x * sc, v.y * sc));
    o.y = h2u(__floats2half2_rn(v.z * sc, v.w * sc));
    *reinterpret_cast<uint2*>(g_xh + (size_t)row * DIM + t * 4) = o;
}

// ===================== Kernel 1b: features fp32 -> fp16 =====================
__global__ void kconv(const float* __restrict__ f) {
    size_t i = ((size_t)blockIdx.x * 256 + threadIdx.x) * 4;
    float4 a = *reinterpret_cast<const float4*>(f + i);
    uint2 o;
    o.x = h2u(__floats2half2_rn(a.x, a.y));
    o.y = h2u(__floats2half2_rn(a.z, a.w));
    *reinterpret_cast<uint2*>(g_fh + i) = o;
}

// ===================== Kernel 1c: target logits (full fp32) =====================
__global__ void ktgt(const float* __restrict__ x, const float* __restrict__ feats,
                     const long long* __restrict__ ctgt) {
    int row = blockIdx.x;
    int t = threadIdx.x;  // 256 threads, 4 floats each
    long long tg64 = ctgt[row];
    int tg = (int)(tg64 < 0 ? 0 : (tg64 >= NSAMP ? NSAMP - 1 : tg64));
    float4 a = reinterpret_cast<const float4*>(x + (size_t)row * DIM)[t];
    float4 b = reinterpret_cast<const float4*>(feats + (size_t)tg * DIM)[t];
    float s = a.x * b.x + a.y * b.y + a.z * b.z + a.w * b.w;
    #pragma unroll
    for (int o = 16; o; o >>= 1) s += __shfl_xor_sync(~0u, s, o);
    __shared__ float sw[8];
    if ((t & 31) == 0) sw[t >> 5] = s;
    __syncthreads();
    if (t == 0) {
        float tot = sw[0] + sw[1] + sw[2] + sw[3] + sw[4] + sw[5] + sw[6] + sw[7];
        g_tlogit[row] = tot * g_rnorm[row] * TEMP_INV;
    }
}

// ===================== Kernel 2: HMMA main, 64x64 warp tiles ================
__device__ __forceinline__ void load_chunk(int m0, int n0, int c,
                                           uint32_t stA, uint32_t stB, int t) {
    const int k0 = c * KC;
    const __half* As = g_xh + (size_t)m0 * DIM + k0;
    const __half* Bs = g_fh + (size_t)n0 * DIM + k0;
    #pragma unroll
    for (int it = 0; it < 8; it++) {              // A: 128 rows x 128B, 128 thr
        int idx = it * 128 + t;
        int r = idx >> 3, cc = idx & 7;
        cp16(stA + (uint32_t)(r * (SLD * 2) + cc * 16), As + (size_t)r * DIM + cc * 8);
    }
    #pragma unroll
    for (int it = 0; it < 8; it++) {              // B: 128 rows x 128B
        int idx = it * 128 + t;
        int r = idx >> 3, cc = idx & 7;
        cp16(stB + (uint32_t)(r * (SLD * 2) + cc * 16), Bs + (size_t)r * DIM + cc * 8);
    }
    CP_COMMIT();
}

__global__ __launch_bounds__(128, 2)
void kmain() {
    extern __shared__ __align__(16) char dyn[];
    __shared__ float s_rowsum[2][MT];

    const int t = threadIdx.x;                // 128 threads = 4 warps (2m x 2n)
    const int lane = t & 31, warp = t >> 5;
    const int wm = warp >> 1;                 // 0..1, rows wm*64
    const int wn = warp & 1;                  // 0..1, cols wn*64
    const int m0 = blockIdx.x * MT;
    const int nti = blockIdx.y;
    const int n0 = nti * NT;

    const uint32_t base = smem_u32(dyn);

    const uint32_t a_row  = (uint32_t)(wm * 64 + (lane & 15));
    const uint32_t a_coff = (uint32_t)((lane >> 4) * 8);
    const uint32_t b_row  = (uint32_t)(wn * 64 + ((lane >> 4) * 8) + (lane & 7));
    const uint32_t b_coff = (uint32_t)(((lane >> 3) & 1) * 8);

    float c[4][8][4];                        // 4 m-frags x 8 n-frags x 4
    #pragma unroll
    for (int i = 0; i < 4; i++)
        #pragma unroll
        for (int j = 0; j < 8; j++)
            #pragma unroll
            for (int q = 0; q < 4; q++) c[i][j][q] = 0.f;

    load_chunk(m0, n0, 0, base,       base + ASTG,       t);
    load_chunk(m0, n0, 1, base + STG, base + STG + ASTG, t);

    uint32_t a[2][4][4], b[2][4][4];         // ks double buffer

    #pragma unroll 1
    for (int i = 0; i < NKC; i++) {
        if (i < NKC - 2) { CP_WAIT(1); } else { CP_WAIT(0); }
        __syncthreads();
        if (i + 2 < NKC) {
            const int sj = (i + 2) % 3;
            load_chunk(m0, n0, i + 2, base + sj * STG, base + sj * STG + ASTG, t);
        }
        const uint32_t sA = base + (uint32_t)(i % 3) * STG;
        const uint32_t sB = sA + ASTG;

        // preload ks=0 fragments
        #pragma unroll
        for (int mt = 0; mt < 4; mt++)
            ldsm_x4(a[0][mt][0], a[0][mt][1], a[0][mt][2], a[0][mt][3],
                    sA + ((a_row + mt * 16) * SLD + a_coff) * 2u);
        #pragma unroll
        for (int np = 0; np < 4; np++)
            ldsm_x4(b[0][np][0], b[0][np][1], b[0][np][2], b[0][np][3],
                    sB + ((b_row + np * 16) * SLD + b_coff) * 2u);

        #pragma unroll
        for (int ks = 0; ks < 4; ks++) {
            const int cur = ks & 1, nxt = cur ^ 1;
            if (ks < 3) {
                #pragma unroll
                for (int mt = 0; mt < 4; mt++)
                    ldsm_x4(a[nxt][mt][0], a[nxt][mt][1], a[nxt][mt][2], a[nxt][mt][3],
                            sA + ((a_row + mt * 16) * SLD + (ks + 1) * 16 + a_coff) * 2u);
                #pragma unroll
                for (int np = 0; np < 4; np++)
                    ldsm_x4(b[nxt][np][0], b[nxt][np][1], b[nxt][np][2], b[nxt][np][3],
                            sB + ((b_row + np * 16) * SLD + (ks + 1) * 16 + b_coff) * 2u);
            }
            #pragma unroll
            for (int mt = 0; mt < 4; mt++)
                #pragma unroll
                for (int np = 0; np < 4; np++) {
                    mma_f16(c[mt][2*np][0], c[mt][2*np][1], c[mt][2*np][2], c[mt][2*np][3],
                            a[cur][mt][0], a[cur][mt][1], a[cur][mt][2], a[cur][mt][3],
                            b[cur][np][0], b[cur][np][1]);
                    mma_f16(c[mt][2*np+1][0], c[mt][2*np+1][1], c[mt][2*np+1][2], c[mt][2*np+1][3],
                            a[cur][mt][0], a[cur][mt][1], a[cur][mt][2], a[cur][mt][3],
                            b[cur][np][2], b[cur][np][3]);
                }
        }
    }

    // ---- epilogue: exp-sum from register fragments ----
    float accrow[8];
    #pragma unroll
    for (int mt = 0; mt < 4; mt++)
        #pragma unroll
        for (int h = 0; h < 2; h++) {
            float rs = 0.f;
            #pragma unroll
            for (int ntl = 0; ntl < 8; ntl++)
                #pragma unroll
                for (int jc = 0; jc < 2; jc++) {
                    float v = c[mt][ntl][h * 2 + jc];
                    float e;
                    asm("ex2.approx.f32 %0, %1;" : "=f"(e) : "f"(v * EXP_SCALE));
                    rs += e;
                }
            accrow[mt * 2 + h] = rs;
        }
    #pragma unroll
    for (int i = 0; i < 8; i++) {
        float v = accrow[i];
        v += __shfl_xor_sync(~0u, v, 1);
        v += __shfl_xor_sync(~0u, v, 2);
        if ((lane & 3) == 0) {
            int row = wm * 64 + (i >> 1) * 16 + (lane >> 2) + (i & 1) * 8;
            s_rowsum[wn][row] = v;
        }
    }
    __syncthreads();
    if (t < MT)
        g_partial[(size_t)(m0 + t) * NTILES + nti] = s_rowsum[0][t] + s_rowsum[1][t];
}

// ===================== Kernel 3: final reduce (2-stage, deterministic) ======
__global__ void kfin1() {          // grid 32, block 256
    int b = blockIdx.x, t = threadIdx.x, w = t >> 5, lane = t & 31;
    float acc = 0.f;
    for (int r0 = w; r0 < 128; r0 += 8) {
        int row = b * 128 + r0;
        const float* p = g_partial + (size_t)row * NTILES;
        float s = 0.f;
        #pragma unroll 4
        for (int i = lane; i < NTILES; i += 32) s += p[i];
        #pragma unroll
        for (int o = 16; o; o >>= 1) s += __shfl_xor_sync(~0u, s, o);
        if (lane == 0) acc += logf(s) - g_tlogit[row];
    }
    __shared__ float sw[8];
    if (lane == 0) sw[w] = acc;
    __syncthreads();
    if (t == 0) {
        float v = 0.f;
        #pragma unroll
        for (int i = 0; i < 8; i++) v += sw[i];
        g_bsum[b] = v;
    }
}
__global__ void kfin2(float* __restrict__ out) {
    int t = threadIdx.x;  // 32
    float v = g_bsum[t];
    #pragma unroll
    for (int o = 16; o; o >>= 1) v += __shfl_xor_sync(~0u, v, o);
    if (t == 0) out[0] = v * (1.0f / BATCH);
}

// ===========================================================================
extern "C" void kernel_launch(void* const* d_in, const int* in_sizes, int n_in,
                              void* d_out, int out_size) {
    const float*     inputs = (const float*)d_in[0];
    const long long* ctgt   = (const long long*)d_in[2];
    const float*     feats  = (const float*)d_in[3];
    float* out = (float*)d_out;

    cudaFuncSetAttribute(kmain, cudaFuncAttributeMaxDynamicSharedMemorySize, SMEM_DYN);

    knorm<<<BATCH, 256>>>(inputs);
    kconv<<<(NSAMP * DIM / 4) / 256, 256>>>(feats);
    ktgt<<<BATCH, 256>>>(inputs, feats, ctgt);
    dim3 grid(MTILES, NTILES);   // x = m (fast): CTAs sharing a B tile run together
    kmain<<<grid, 128, SMEM_DYN>>>();
    kfin1<<<32, 256>>>();
    kfin2<<<1, 32>>>(out);
}

// round 7
// speedup vs baseline: 2.0701x; 1.2189x over previous
#include <cuda_runtime.h>
#include <cuda_fp16.h>
#include <cstdint>

#define BATCH   4096
#define DIM     1024
#define NSAMP   32768
#define MT      128
#define NT      128
#define KC      64                   // K chunk (fp16) = 128B row
#define NKC     (DIM / KC)           // 16
#define MTILES  (BATCH / MT)         // 32
#define NTILES  (NSAMP / NT)         // 256
#define BLKB    16384                // one (tile, chunk) block: 128 rows x 128B
#define STG     (2 * BLKB)           // A + B per stage = 32KB
#define SMEM_DYN (3 * STG)           // 96KB
#define TEMP_INV 20.0f
#define EXP_SCALE (20.0f * 1.4426950408889634f)

// ---- persistent device scratch (chunk-tiled, pre-swizzled layouts) ----
// g_xh: [MTILES][NKC][128 rows][64 halfs]  (16KB blocks, SW128-swizzled)
// g_fh: [NTILES][NKC][128 rows][64 halfs]
__device__ __align__(16) __half g_xh[(size_t)BATCH * DIM];
__device__ __align__(16) __half g_fh[(size_t)NSAMP * DIM];
__device__ float g_partial[(size_t)BATCH * NTILES];
__device__ float g_tlogit[BATCH];
__device__ float g_rnorm[BATCH];
__device__ float g_bsum[32];

// =============================== helpers ===============================
__device__ __forceinline__ uint32_t smem_u32(const void* p) {
    return (uint32_t)__cvta_generic_to_shared(p);
}
__device__ __forceinline__ uint32_t h2u(__half2 v) {
    return *reinterpret_cast<uint32_t*>(&v);
}
__device__ __forceinline__ void mbar_init(uint32_t mb, uint32_t cnt) {
    asm volatile("mbarrier.init.shared.b64 [%0], %1;" :: "r"(mb), "r"(cnt) : "memory");
}
__device__ __forceinline__ void mbar_wait(uint32_t mb, uint32_t parity) {
    asm volatile(
        "{\n\t.reg .pred P;\n"
        "W%=:\n\t"
        "mbarrier.try_wait.parity.shared.b64 P, [%0], %1, 0x989680;\n\t"
        "@!P bra W%=;\n\t}"
        :: "r"(mb), "r"(parity) : "memory");
}
#define MB_EXPECT(mb, b) \
    asm volatile("mbarrier.arrive.expect_tx.shared.b64 _, [%0], %1;" :: "r"(mb), "r"((uint32_t)(b)) : "memory")
#define MB_ARRIVE(mb) \
    asm volatile("mbarrier.arrive.shared.b64 _, [%0];" :: "r"(mb) : "memory")
__device__ __forceinline__ void bulk_g2s(uint32_t dst, const void* src, uint32_t bytes, uint32_t mb) {
    asm volatile(
        "cp.async.bulk.shared::cluster.global.mbarrier::complete_tx::bytes [%0], [%1], %2, [%3];"
        :: "r"(dst), "l"(src), "r"(bytes), "r"(mb) : "memory");
}
__device__ __forceinline__ void ldsm_x4(uint32_t& r0, uint32_t& r1, uint32_t& r2, uint32_t& r3,
                                        uint32_t addr) {
    asm volatile("ldmatrix.sync.aligned.m8n8.x4.shared.b16 {%0,%1,%2,%3}, [%4];"
                 : "=r"(r0), "=r"(r1), "=r"(r2), "=r"(r3) : "r"(addr));
}
__device__ __forceinline__ void mma_f16(float& c0, float& c1, float& c2, float& c3,
                                        uint32_t a0, uint32_t a1, uint32_t a2, uint32_t a3,
                                        uint32_t b0, uint32_t b1) {
    asm volatile(
        "mma.sync.aligned.m16n8k16.row.col.f32.f16.f16.f32 "
        "{%0,%1,%2,%3}, {%4,%5,%6,%7}, {%8,%9}, {%0,%1,%2,%3};"
        : "+f"(c0), "+f"(c1), "+f"(c2), "+f"(c3)
        : "r"(a0), "r"(a1), "r"(a2), "r"(a3), "r"(b0), "r"(b1));
}

// swizzled in-block byte offset for (row r, byte kb within 128B row)
__device__ __forceinline__ uint32_t swz(uint32_t r, uint32_t kb) {
    return r * 128u + (kb ^ ((r & 7u) << 4));
}

// ===================== Kernel 1: normalize inputs -> tiled fp16 =============
__global__ void knorm(const float* __restrict__ x) {
    int row = blockIdx.x;
    int t = threadIdx.x;  // 256 threads, 4 floats each
    const float4* xr = reinterpret_cast<const float4*>(x + (size_t)row * DIM);
    float4 v = xr[t];
    float ss = v.x * v.x + v.y * v.y + v.z * v.z + v.w * v.w;
    #pragma unroll
    for (int o = 16; o; o >>= 1) ss += __shfl_xor_sync(~0u, ss, o);
    __shared__ float sw[8];
    if ((t & 31) == 0) sw[t >> 5] = ss;
    __syncthreads();
    float tot = sw[0] + sw[1] + sw[2] + sw[3] + sw[4] + sw[5] + sw[6] + sw[7];
    float sc = rsqrtf(fmaxf(tot, 1e-24f));
    if (t == 0) g_rnorm[row] = sc;
    uint2 o;
    o.x = h2u(__floats2half2_rn(v.x * sc, v.y * sc));
    o.y = h2u(__floats2half2_rn(v.z * sc, v.w * sc));
    // tiled+swizzled dst: block = (row/128)*16 + chunk, chunk = (t*4)/64
    uint32_t r = (uint32_t)(row & 127);
    uint32_t blk = (uint32_t)((row >> 7) * NKC + (t >> 4));
    uint32_t off = blk * BLKB + swz(r, (uint32_t)(t & 15) * 8u);
    *reinterpret_cast<uint2*>(reinterpret_cast<char*>(g_xh) + off) = o;
}

// ===================== Kernel 1b: features fp32 -> tiled fp16 ===============
__global__ void kconv(const float* __restrict__ f) {
    size_t gid = (size_t)blockIdx.x * 256 + threadIdx.x;
    size_t e = gid * 4;
    float4 a = *reinterpret_cast<const float4*>(f + e);
    uint2 o;
    o.x = h2u(__floats2half2_rn(a.x, a.y));
    o.y = h2u(__floats2half2_rn(a.z, a.w));
    uint32_t n = (uint32_t)(e >> 10), col = (uint32_t)(e & 1023);
    uint32_t blk = (n >> 7) * NKC + (col >> 6);
    uint32_t off = blk * BLKB + swz(n & 127u, (col & 63u) * 2u);
    *reinterpret_cast<uint2*>(reinterpret_cast<char*>(g_fh) + off) = o;
}

// ===================== Kernel 1c: target logits (full fp32) =================
__global__ void ktgt(const float* __restrict__ x, const float* __restrict__ feats,
                     const long long* __restrict__ ctgt) {
    int row = blockIdx.x;
    int t = threadIdx.x;  // 256
    long long tg64 = ctgt[row];
    int tg = (int)(tg64 < 0 ? 0 : (tg64 >= NSAMP ? NSAMP - 1 : tg64));
    float4 a = reinterpret_cast<const float4*>(x + (size_t)row * DIM)[t];
    float4 b = reinterpret_cast<const float4*>(feats + (size_t)tg * DIM)[t];
    float s = a.x * b.x + a.y * b.y + a.z * b.z + a.w * b.w;
    #pragma unroll
    for (int o = 16; o; o >>= 1) s += __shfl_xor_sync(~0u, s, o);
    __shared__ float sw[8];
    if ((t & 31) == 0) sw[t >> 5] = s;
    __syncthreads();
    if (t == 0) {
        float tot = sw[0] + sw[1] + sw[2] + sw[3] + sw[4] + sw[5] + sw[6] + sw[7];
        g_tlogit[row] = tot * g_rnorm[row] * TEMP_INV;
    }
}

// ===================== Kernel 2: HMMA main, bulk-copy pipeline ==============
__global__ __launch_bounds__(128, 2)
void kmain() {
    extern __shared__ __align__(1024) char dyn[];
    __shared__ __align__(8) uint64_t s_mb[6];   // [0..2] data, [3..5] free
    __shared__ float s_rowsum[2][MT];

    const int t = threadIdx.x;                // 128 threads = 4 warps (2m x 2n)
    const int lane = t & 31, warp = t >> 5;
    const int wm = warp >> 1;
    const int wn = warp & 1;
    const int nti = blockIdx.y;

    const uint32_t base = smem_u32(dyn);
    const uint32_t mbd = smem_u32(&s_mb[0]);
    const uint32_t mbf = smem_u32(&s_mb[3]);

    const char* srcA = reinterpret_cast<const char*>(g_xh) + (size_t)blockIdx.x * NKC * BLKB;
    const char* srcB = reinterpret_cast<const char*>(g_fh) + (size_t)nti * NKC * BLKB;

    if (t == 0) {
        #pragma unroll
        for (int s = 0; s < 3; s++) { mbar_init(mbd + s * 8, 1); mbar_init(mbf + s * 8, 4); }
    }
    __syncthreads();

    // prologue: issue chunks 0,1 (2-deep prefetch)
    if (t == 0) {
        #pragma unroll
        for (int c = 0; c < 2; c++) {
            MB_EXPECT(mbd + c * 8, STG);
            bulk_g2s(base + c * STG,        srcA + (size_t)c * BLKB, BLKB, mbd + c * 8);
            bulk_g2s(base + c * STG + BLKB, srcB + (size_t)c * BLKB, BLKB, mbd + c * 8);
        }
    }

    // per-lane swizzled addressing
    const uint32_t a_r    = (uint32_t)(wm * 64 + (lane & 15));
    const uint32_t a_base = a_r * 128u;
    const uint32_t a_xor  = (a_r & 7u) << 4;
    const uint32_t a_cb   = (uint32_t)((lane >> 4) * 16);
    const uint32_t b_r    = (uint32_t)(wn * 64 + ((lane >> 4) * 8) + (lane & 7));
    const uint32_t b_base = b_r * 128u;
    const uint32_t b_xor  = (b_r & 7u) << 4;
    const uint32_t b_cb   = (uint32_t)(((lane >> 3) & 1) * 16);

    float c[4][8][4];
    #pragma unroll
    for (int i = 0; i < 4; i++)
        #pragma unroll
        for (int j = 0; j < 8; j++)
            #pragma unroll
            for (int q = 0; q < 4; q++) c[i][j][q] = 0.f;

    uint32_t a[2][4][4], b[2][4][4];

    #pragma unroll 1
    for (int i = 0; i < NKC; i++) {
        const int s = i % 3;
        // producer: issue chunk i+2 into buffer (i+2)%3 (freed during chunk i-1)
        if (t == 0 && i + 2 < NKC) {
            const int sf = (i + 2) % 3;
            if (i >= 1) mbar_wait(mbf + sf * 8, (uint32_t)(((i - 1) / 3) & 1));
            MB_EXPECT(mbd + sf * 8, STG);
            bulk_g2s(base + sf * STG,        srcA + (size_t)(i + 2) * BLKB, BLKB, mbd + sf * 8);
            bulk_g2s(base + sf * STG + BLKB, srcB + (size_t)(i + 2) * BLKB, BLKB, mbd + sf * 8);
        }
        // consumer: wait HW tx completion for chunk i
        mbar_wait(mbd + s * 8, (uint32_t)((i / 3) & 1));

        const uint32_t sA = base + (uint32_t)s * STG;
        const uint32_t sB = sA + BLKB;

        #pragma unroll
        for (int mt = 0; mt < 4; mt++)
            ldsm_x4(a[0][mt][0], a[0][mt][1], a[0][mt][2], a[0][mt][3],
                    sA + a_base + mt * 2048u + (a_cb ^ a_xor));
        #pragma unroll
        for (int np = 0; np < 4; np++)
            ldsm_x4(b[0][np][0], b[0][np][1], b[0][np][2], b[0][np][3],
                    sB + b_base + np * 2048u + (b_cb ^ b_xor));

        #pragma unroll
        for (int ks = 0; ks < 4; ks++) {
            const int cur = ks & 1, nxt = cur ^ 1;
            if (ks < 3) {
                const uint32_t kb = (uint32_t)((ks + 1) * 32);
                #pragma unroll
                for (int mt = 0; mt < 4; mt++)
                    ldsm_x4(a[nxt][mt][0], a[nxt][mt][1], a[nxt][mt][2], a[nxt][mt][3],
                            sA + a_base + mt * 2048u + ((kb + a_cb) ^ a_xor));
                #pragma unroll
                for (int np = 0; np < 4; np++)
                    ldsm_x4(b[nxt][np][0], b[nxt][np][1], b[nxt][np][2], b[nxt][np][3],
                            sB + b_base + np * 2048u + ((kb + b_cb) ^ b_xor));
                if (ks == 2 && lane == 0) MB_ARRIVE(mbf + s * 8);  // last reads of buffer s done
            }
            #pragma unroll
            for (int mt = 0; mt < 4; mt++)
                #pragma unroll
                for (int np = 0; np < 4; np++) {
                    mma_f16(c[mt][2*np][0], c[mt][2*np][1], c[mt][2*np][2], c[mt][2*np][3],
                            a[cur][mt][0], a[cur][mt][1], a[cur][mt][2], a[cur][mt][3],
                            b[cur][np][0], b[cur][np][1]);
                    mma_f16(c[mt][2*np+1][0], c[mt][2*np+1][1], c[mt][2*np+1][2], c[mt][2*np+1][3],
                            a[cur][mt][0], a[cur][mt][1], a[cur][mt][2], a[cur][mt][3],
                            b[cur][np][2], b[cur][np][3]);
                }
        }
    }

    // ---- epilogue: exp-sum from register fragments ----
    float accrow[8];
    #pragma unroll
    for (int mt = 0; mt < 4; mt++)
        #pragma unroll
        for (int h = 0; h < 2; h++) {
            float rs = 0.f;
            #pragma unroll
            for (int ntl = 0; ntl < 8; ntl++)
                #pragma unroll
                for (int jc = 0; jc < 2; jc++) {
                    float v = c[mt][ntl][h * 2 + jc];
                    float e;
                    asm("ex2.approx.f32 %0, %1;" : "=f"(e) : "f"(v * EXP_SCALE));
                    rs += e;
                }
            accrow[mt * 2 + h] = rs;
        }
    #pragma unroll
    for (int i = 0; i < 8; i++) {
        float v = accrow[i];
        v += __shfl_xor_sync(~0u, v, 1);
        v += __shfl_xor_sync(~0u, v, 2);
        if ((lane & 3) == 0) {
            int row = wm * 64 + (i >> 1) * 16 + (lane >> 2) + (i & 1) * 8;
            s_rowsum[wn][row] = v;
        }
    }
    __syncthreads();
    if (t < MT)
        g_partial[(size_t)(blockIdx.x * MT + t) * NTILES + nti] =
            s_rowsum[0][t] + s_rowsum[1][t];
}

// ===================== Kernel 3: final reduce (2-stage, deterministic) ======
__global__ void kfin1() {          // grid 32, block 256
    int bb = blockIdx.x, t = threadIdx.x, w = t >> 5, lane = t & 31;
    float acc = 0.f;
    for (int r0 = w; r0 < 128; r0 += 8) {
        int row = bb * 128 + r0;
        const float* p = g_partial + (size_t)row * NTILES;
        float s = 0.f;
        #pragma unroll 4
        for (int i = lane; i < NTILES; i += 32) s += p[i];
        #pragma unroll
        for (int o = 16; o; o >>= 1) s += __shfl_xor_sync(~0u, s, o);
        if (lane == 0) acc += logf(s) - g_tlogit[row];
    }
    __shared__ float sw[8];
    if (lane == 0) sw[w] = acc;
    __syncthreads();
    if (t == 0) {
        float v = 0.f;
        #pragma unroll
        for (int i = 0; i < 8; i++) v += sw[i];
        g_bsum[bb] = v;
    }
}
__global__ void kfin2(float* __restrict__ out) {
    int t = threadIdx.x;  // 32
    float v = g_bsum[t];
    #pragma unroll
    for (int o = 16; o; o >>= 1) v += __shfl_xor_sync(~0u, v, o);
    if (t == 0) out[0] = v * (1.0f / BATCH);
}

// ===========================================================================
extern "C" void kernel_launch(void* const* d_in, const int* in_sizes, int n_in,
                              void* d_out, int out_size) {
    const float*     inputs = (const float*)d_in[0];
    const long long* ctgt   = (const long long*)d_in[2];
    const float*     feats  = (const float*)d_in[3];
    float* out = (float*)d_out;

    cudaFuncSetAttribute(kmain, cudaFuncAttributeMaxDynamicSharedMemorySize, SMEM_DYN);

    knorm<<<BATCH, 256>>>(inputs);
    kconv<<<(NSAMP * DIM / 4) / 256, 256>>>(feats);
    ktgt<<<BATCH, 256>>>(inputs, feats, ctgt);
    dim3 grid(MTILES, NTILES);   // x = m (fast): CTAs sharing a B tile run together
    kmain<<<grid, 128, SMEM_DYN>>>();
    kfin1<<<32, 256>>>();
    kfin2<<<1, 32>>>(out);
}

// round 8
// speedup vs baseline: 2.0732x; 1.0015x over previous
#include <cuda_runtime.h>
#include <cuda_fp16.h>
#include <cstdint>

#define BATCH   4096
#define DIM     1024
#define NSAMP   32768
#define MT      128
#define NT      128
#define KC      64                   // K chunk (fp16) = 128B row
#define NKC     (DIM / KC)           // 16
#define MTILES  (BATCH / MT)         // 32
#define NTILES  (NSAMP / NT)         // 256
#define BLKB    16384                // one (tile, chunk) block: 128 rows x 128B
#define STG     (2 * BLKB)           // A + B per stage = 32KB
#define SMEM_DYN (3 * STG)           // 96KB
#define TEMP_INV 20.0f
#define EXP_SCALE (20.0f * 1.4426950408889634f)

// prep kernel block ranges
#define NB_CONV 8192                 // feats convert: 16 elems/thread
#define NB_NORM 4096
#define NB_TGT  4096

// ---- persistent device scratch (chunk-tiled, pre-swizzled layouts) ----
__device__ __align__(16) __half g_xh[(size_t)BATCH * DIM];
__device__ __align__(16) __half g_fh[(size_t)NSAMP * DIM];
__device__ float g_partial[(size_t)BATCH * NTILES * 2];   // [row][nti][wn]
__device__ float g_tlogit[BATCH];
__device__ float g_bsum[32];

// =============================== helpers ===============================
__device__ __forceinline__ uint32_t smem_u32(const void* p) {
    return (uint32_t)__cvta_generic_to_shared(p);
}
__device__ __forceinline__ uint32_t h2u(__half2 v) {
    return *reinterpret_cast<uint32_t*>(&v);
}
__device__ __forceinline__ void mbar_init(uint32_t mb, uint32_t cnt) {
    asm volatile("mbarrier.init.shared.b64 [%0], %1;" :: "r"(mb), "r"(cnt) : "memory");
}
__device__ __forceinline__ void mbar_wait(uint32_t mb, uint32_t parity) {
    asm volatile(
        "{\n\t.reg .pred P;\n"
        "W%=:\n\t"
        "mbarrier.try_wait.parity.shared.b64 P, [%0], %1, 0x989680;\n\t"
        "@!P bra W%=;\n\t}"
        :: "r"(mb), "r"(parity) : "memory");
}
#define MB_EXPECT(mb, b) \
    asm volatile("mbarrier.arrive.expect_tx.shared.b64 _, [%0], %1;" :: "r"(mb), "r"((uint32_t)(b)) : "memory")
#define MB_ARRIVE(mb) \
    asm volatile("mbarrier.arrive.shared.b64 _, [%0];" :: "r"(mb) : "memory")
__device__ __forceinline__ void bulk_g2s(uint32_t dst, const void* src, uint32_t bytes, uint32_t mb) {
    asm volatile(
        "cp.async.bulk.shared::cluster.global.mbarrier::complete_tx::bytes [%0], [%1], %2, [%3];"
        :: "r"(dst), "l"(src), "r"(bytes), "r"(mb) : "memory");
}
__device__ __forceinline__ void ldsm_x4(uint32_t& r0, uint32_t& r1, uint32_t& r2, uint32_t& r3,
                                        uint32_t addr) {
    asm volatile("ldmatrix.sync.aligned.m8n8.x4.shared.b16 {%0,%1,%2,%3}, [%4];"
                 : "=r"(r0), "=r"(r1), "=r"(r2), "=r"(r3) : "r"(addr));
}
__device__ __forceinline__ void mma_f16(float& c0, float& c1, float& c2, float& c3,
                                        uint32_t a0, uint32_t a1, uint32_t a2, uint32_t a3,
                                        uint32_t b0, uint32_t b1) {
    asm volatile(
        "mma.sync.aligned.m16n8k16.row.col.f32.f16.f16.f32 "
        "{%0,%1,%2,%3}, {%4,%5,%6,%7}, {%8,%9}, {%0,%1,%2,%3};"
        : "+f"(c0), "+f"(c1), "+f"(c2), "+f"(c3)
        : "r"(a0), "r"(a1), "r"(a2), "r"(a3), "r"(b0), "r"(b1));
}
// swizzled in-block byte offset for (row r, byte kb within 128B row)
__device__ __forceinline__ uint32_t swz(uint32_t r, uint32_t kb) {
    return r * 128u + (kb ^ ((r & 7u) << 4));
}

// ===================== Kernel 1: fused prep =====================
// blocks [0, NB_CONV)                : feats fp32 -> tiled fp16 (16 elems/thr)
// blocks [NB_CONV, +NB_NORM)         : normalize inputs -> tiled fp16
// blocks [NB_CONV+NB_NORM, +NB_TGT)  : target logits (fp32, own norm)
__global__ void kprep(const float* __restrict__ x, const float* __restrict__ feats,
                      const long long* __restrict__ ctgt) {
    int b = blockIdx.x;
    int t = threadIdx.x;  // 256

    if (b < NB_CONV) {
        size_t e0 = ((size_t)b * 256 + t) * 16;
        #pragma unroll
        for (int j = 0; j < 4; j++) {
            size_t e = e0 + j * 4;
            float4 a = *reinterpret_cast<const float4*>(feats + e);
            uint2 o;
            o.x = h2u(__floats2half2_rn(a.x, a.y));
            o.y = h2u(__floats2half2_rn(a.z, a.w));
            uint32_t n = (uint32_t)(e >> 10), col = (uint32_t)(e & 1023);
            uint32_t blk = (n >> 7) * NKC + (col >> 6);
            uint32_t off = blk * BLKB + swz(n & 127u, (col & 63u) * 2u);
            *reinterpret_cast<uint2*>(reinterpret_cast<char*>(g_fh) + off) = o;
        }
        return;
    }

    if (b < NB_CONV + NB_NORM) {
        int row = b - NB_CONV;
        const float4* xr = reinterpret_cast<const float4*>(x + (size_t)row * DIM);
        float4 v = xr[t];
        float ss = v.x * v.x + v.y * v.y + v.z * v.z + v.w * v.w;
        #pragma unroll
        for (int o = 16; o; o >>= 1) ss += __shfl_xor_sync(~0u, ss, o);
        __shared__ float sw1[8];
        if ((t & 31) == 0) sw1[t >> 5] = ss;
        __syncthreads();
        float tot = sw1[0] + sw1[1] + sw1[2] + sw1[3] + sw1[4] + sw1[5] + sw1[6] + sw1[7];
        float sc = rsqrtf(fmaxf(tot, 1e-24f));
        uint2 o;
        o.x = h2u(__floats2half2_rn(v.x * sc, v.y * sc));
        o.y = h2u(__floats2half2_rn(v.z * sc, v.w * sc));
        uint32_t r = (uint32_t)(row & 127);
        uint32_t blk = (uint32_t)((row >> 7) * NKC + (t >> 4));
        uint32_t off = blk * BLKB + swz(r, (uint32_t)(t & 15) * 8u);
        *reinterpret_cast<uint2*>(reinterpret_cast<char*>(g_xh) + off) = o;
        return;
    }

    {   // target logit, fully fp32, computes its own norm
        int row = b - NB_CONV - NB_NORM;
        long long tg64 = ctgt[row];
        int tg = (int)(tg64 < 0 ? 0 : (tg64 >= NSAMP ? NSAMP - 1 : tg64));
        float4 a = reinterpret_cast<const float4*>(x + (size_t)row * DIM)[t];
        float4 bb = reinterpret_cast<const float4*>(feats + (size_t)tg * DIM)[t];
        float s  = a.x * bb.x + a.y * bb.y + a.z * bb.z + a.w * bb.w;
        float ss = a.x * a.x + a.y * a.y + a.z * a.z + a.w * a.w;
        #pragma unroll
        for (int o = 16; o; o >>= 1) {
            s  += __shfl_xor_sync(~0u, s, o);
            ss += __shfl_xor_sync(~0u, ss, o);
        }
        __shared__ float sw2[16];
        if ((t & 31) == 0) { sw2[t >> 5] = s; sw2[8 + (t >> 5)] = ss; }
        __syncthreads();
        if (t == 0) {
            float ts = 0.f, tss = 0.f;
            #pragma unroll
            for (int i = 0; i < 8; i++) { ts += sw2[i]; tss += sw2[8 + i]; }
            g_tlogit[row] = ts * rsqrtf(fmaxf(tss, 1e-24f)) * TEMP_INV;
        }
    }
}

// ===================== Kernel 2: HMMA main, cross-chunk pipelined ===========
__global__ __launch_bounds__(128, 2)
void kmain() {
    extern __shared__ __align__(1024) char dyn[];
    __shared__ __align__(8) uint64_t s_mb[6];   // [0..2] data, [3..5] free

    const int t = threadIdx.x;                // 128 threads = 4 warps (2m x 2n)
    const int lane = t & 31, warp = t >> 5;
    const int wm = warp >> 1;
    const int wn = warp & 1;
    const int nti = blockIdx.y;

    const uint32_t base = smem_u32(dyn);
    const uint32_t mbd = smem_u32(&s_mb[0]);
    const uint32_t mbf = smem_u32(&s_mb[3]);

    const char* srcA = reinterpret_cast<const char*>(g_xh) + (size_t)blockIdx.x * NKC * BLKB;
    const char* srcB = reinterpret_cast<const char*>(g_fh) + (size_t)nti * NKC * BLKB;

    if (t == 0) {
        #pragma unroll
        for (int s = 0; s < 3; s++) { mbar_init(mbd + s * 8, 1); mbar_init(mbf + s * 8, 4); }
    }
    __syncthreads();

    if (t == 0) {
        #pragma unroll
        for (int c = 0; c < 2; c++) {
            MB_EXPECT(mbd + c * 8, STG);
            bulk_g2s(base + c * STG,        srcA + (size_t)c * BLKB, BLKB, mbd + c * 8);
            bulk_g2s(base + c * STG + BLKB, srcB + (size_t)c * BLKB, BLKB, mbd + c * 8);
        }
    }

    const uint32_t a_r    = (uint32_t)(wm * 64 + (lane & 15));
    const uint32_t a_base = a_r * 128u;
    const uint32_t a_xor  = (a_r & 7u) << 4;
    const uint32_t a_cb   = (uint32_t)((lane >> 4) * 16);
    const uint32_t b_r    = (uint32_t)(wn * 64 + ((lane >> 4) * 8) + (lane & 7));
    const uint32_t b_base = b_r * 128u;
    const uint32_t b_xor  = (b_r & 7u) << 4;
    const uint32_t b_cb   = (uint32_t)(((lane >> 3) & 1) * 16);

    float c[4][8][4];
    #pragma unroll
    for (int i = 0; i < 4; i++)
        #pragma unroll
        for (int j = 0; j < 8; j++)
            #pragma unroll
            for (int q = 0; q < 4; q++) c[i][j][q] = 0.f;

    uint32_t a[2][4][4], b[2][4][4];

    // steady-state seed: wait chunk0, preload its ks0 frags into buf0
    mbar_wait(mbd, 0);
    {
        const uint32_t sA = base, sB = base + BLKB;
        #pragma unroll
        for (int mt = 0; mt < 4; mt++)
            ldsm_x4(a[0][mt][0], a[0][mt][1], a[0][mt][2], a[0][mt][3],
                    sA + a_base + mt * 2048u + (a_cb ^ a_xor));
        #pragma unroll
        for (int np = 0; np < 4; np++)
            ldsm_x4(b[0][np][0], b[0][np][1], b[0][np][2], b[0][np][3],
                    sB + b_base + np * 2048u + (b_cb ^ b_xor));
    }

    #pragma unroll 1
    for (int i = 0; i < NKC; i++) {
        const int s = i % 3;
        if (t == 0 && i + 2 < NKC) {
            const int sf = (i + 2) % 3;
            if (i >= 1) mbar_wait(mbf + sf * 8, (uint32_t)(((i - 1) / 3) & 1));
            MB_EXPECT(mbd + sf * 8, STG);
            bulk_g2s(base + sf * STG,        srcA + (size_t)(i + 2) * BLKB, BLKB, mbd + sf * 8);
            bulk_g2s(base + sf * STG + BLKB, srcB + (size_t)(i + 2) * BLKB, BLKB, mbd + sf * 8);
        }
        const uint32_t sA = base + (uint32_t)s * STG;
        const uint32_t sB = sA + BLKB;

        #pragma unroll
        for (int ks = 0; ks < 4; ks++) {
            const int cur = ks & 1, nxt = cur ^ 1;
            if (ks < 3) {
                const uint32_t kb = (uint32_t)((ks + 1) * 32);
                #pragma unroll
                for (int mt = 0; mt < 4; mt++)
                    ldsm_x4(a[nxt][mt][0], a[nxt][mt][1], a[nxt][mt][2], a[nxt][mt][3],
                            sA + a_base + mt * 2048u + ((kb + a_cb) ^ a_xor));
                #pragma unroll
                for (int np = 0; np < 4; np++)
                    ldsm_x4(b[nxt][np][0], b[nxt][np][1], b[nxt][np][2], b[nxt][np][3],
                            sB + b_base + np * 2048u + ((kb + b_cb) ^ b_xor));
                if (ks == 2 && lane == 0) MB_ARRIVE(mbf + s * 8);   // last reads of buffer s issued
            } else if (i + 1 < NKC) {
                // cross-chunk: wait next chunk's data (overlaps ks2/ks3 MMA drain), preload its ks0
                const int sn = (i + 1) % 3;
                mbar_wait(mbd + sn * 8, (uint32_t)(((i + 1) / 3) & 1));
                const uint32_t nA = base + (uint32_t)sn * STG;
                const uint32_t nB = nA + BLKB;
                #pragma unroll
                for (int mt = 0; mt < 4; mt++)
                    ldsm_x4(a[nxt][mt][0], a[nxt][mt][1], a[nxt][mt][2], a[nxt][mt][3],
                            nA + a_base + mt * 2048u + (a_cb ^ a_xor));
                #pragma unroll
                for (int np = 0; np < 4; np++)
                    ldsm_x4(b[nxt][np][0], b[nxt][np][1], b[nxt][np][2], b[nxt][np][3],
                            nB + b_base + np * 2048u + (b_cb ^ b_xor));
            }
            #pragma unroll
            for (int mt = 0; mt < 4; mt++)
                #pragma unroll
                for (int np = 0; np < 4; np++) {
                    mma_f16(c[mt][2*np][0], c[mt][2*np][1], c[mt][2*np][2], c[mt][2*np][3],
                            a[cur][mt][0], a[cur][mt][1], a[cur][mt][2], a[cur][mt][3],
                            b[cur][np][0], b[cur][np][1]);
                    mma_f16(c[mt][2*np+1][0], c[mt][2*np+1][1], c[mt][2*np+1][2], c[mt][2*np+1][3],
                            a[cur][mt][0], a[cur][mt][1], a[cur][mt][2], a[cur][mt][3],
                            b[cur][np][2], b[cur][np][3]);
                }
        }
    }

    // ---- epilogue: exp-sum, shuffle-reduce, direct per-wn global write ----
    #pragma unroll
    for (int mt = 0; mt < 4; mt++)
        #pragma unroll
        for (int h = 0; h < 2; h++) {
            float rs = 0.f;
            #pragma unroll
            for (int ntl = 0; ntl < 8; ntl++)
                #pragma unroll
                for (int jc = 0; jc < 2; jc++) {
                    float v = c[mt][ntl][h * 2 + jc];
                    float e;
                    asm("ex2.approx.f32 %0, %1;" : "=f"(e) : "f"(v * EXP_SCALE));
                    rs += e;
                }
            rs += __shfl_xor_sync(~0u, rs, 1);
            rs += __shfl_xor_sync(~0u, rs, 2);
            if ((lane & 3) == 0) {
                int row = blockIdx.x * MT + wm * 64 + mt * 16 + (lane >> 2) + h * 8;
                g_partial[((size_t)row * NTILES + nti) * 2 + wn] = rs;
            }
        }
}

// ===================== Kernel 3: final reduce (2-stage, deterministic) ======
__global__ void kfin1() {          // grid 32, block 256
    int bb = blockIdx.x, t = threadIdx.x, w = t >> 5, lane = t & 31;
    float acc = 0.f;
    for (int r0 = w; r0 < 128; r0 += 8) {
        int row = bb * 128 + r0;
        const float* p = g_partial + (size_t)row * NTILES * 2;
        float s = 0.f;
        #pragma unroll 4
        for (int i = lane; i < NTILES * 2; i += 32) s += p[i];
        #pragma unroll
        for (int o = 16; o; o >>= 1) s += __shfl_xor_sync(~0u, s, o);
        if (lane == 0) acc += logf(s) - g_tlogit[row];
    }
    __shared__ float sw[8];
    if (lane == 0) sw[w] = acc;
    __syncthreads();
    if (t == 0) {
        float v = 0.f;
        #pragma unroll
        for (int i = 0; i < 8; i++) v += sw[i];
        g_bsum[bb] = v;
    }
}
__global__ void kfin2(float* __restrict__ out) {
    int t = threadIdx.x;  // 32
    float v = g_bsum[t];
    #pragma unroll
    for (int o = 16; o; o >>= 1) v += __shfl_xor_sync(~0u, v, o);
    if (t == 0) out[0] = v * (1.0f / BATCH);
}

// ===========================================================================
extern "C" void kernel_launch(void* const* d_in, const int* in_sizes, int n_in,
                              void* d_out, int out_size) {
    const float*     inputs = (const float*)d_in[0];
    const long long* ctgt   = (const long long*)d_in[2];
    const float*     feats  = (const float*)d_in[3];
    float* out = (float*)d_out;

    cudaFuncSetAttribute(kmain, cudaFuncAttributeMaxDynamicSharedMemorySize, SMEM_DYN);

    kprep<<<NB_CONV + NB_NORM + NB_TGT, 256>>>(inputs, feats, ctgt);
    dim3 grid(MTILES, NTILES);   // x = m (fast): CTAs sharing a B tile run together
    kmain<<<grid, 128, SMEM_DYN>>>();
    kfin1<<<32, 256>>>();
    kfin2<<<1, 32>>>(out);
}

// round 9
// speedup vs baseline: 2.0895x; 1.0079x over previous
#include <cuda_runtime.h>
#include <cuda_fp16.h>
#include <cstdint>

#define BATCH   4096
#define DIM     1024
#define NSAMP   32768
#define MT      128
#define NT      128
#define KC      64                   // K chunk (fp16) = 128B row
#define NKC     (DIM / KC)           // 16
#define MTILES  (BATCH / MT)         // 32
#define NTILES  (NSAMP / NT)         // 256
#define BLKB    16384                // one (tile, chunk) block: 128 rows x 128B
#define STG     (2 * BLKB)           // A + B per stage = 32KB
#define SMEM_DYN (3 * STG)           // 96KB
#define TEMP_INV 20.0f
#define EXP_SCALE (20.0f * 1.4426950408889634f)

// prep kernel block ranges
#define NB_CONV 8192                 // feats convert: 16 elems/thread
#define NB_NORM 4096
#define NB_TGT  4096

// ---- persistent device scratch (chunk-tiled, pre-swizzled layouts) ----
__device__ __align__(16) __half g_xh[(size_t)BATCH * DIM];
__device__ __align__(16) __half g_fh[(size_t)NSAMP * DIM];
__device__ float g_partial[(size_t)BATCH * NTILES * 2];   // [row][nti][wn]
__device__ float g_tlogit[BATCH];
__device__ float g_bsum[32];
__device__ unsigned g_cnt;

// =============================== helpers ===============================
__device__ __forceinline__ uint32_t smem_u32(const void* p) {
    return (uint32_t)__cvta_generic_to_shared(p);
}
__device__ __forceinline__ uint32_t h2u(__half2 v) {
    return *reinterpret_cast<uint32_t*>(&v);
}
__device__ __forceinline__ void mbar_init(uint32_t mb, uint32_t cnt) {
    asm volatile("mbarrier.init.shared.b64 [%0], %1;" :: "r"(mb), "r"(cnt) : "memory");
}
__device__ __forceinline__ void mbar_wait(uint32_t mb, uint32_t parity) {
    asm volatile(
        "{\n\t.reg .pred P;\n"
        "W%=:\n\t"
        "mbarrier.try_wait.parity.shared.b64 P, [%0], %1, 0x989680;\n\t"
        "@!P bra W%=;\n\t}"
        :: "r"(mb), "r"(parity) : "memory");
}
#define MB_EXPECT(mb, b) \
    asm volatile("mbarrier.arrive.expect_tx.shared.b64 _, [%0], %1;" :: "r"(mb), "r"((uint32_t)(b)) : "memory")
#define MB_ARRIVE(mb) \
    asm volatile("mbarrier.arrive.shared.b64 _, [%0];" :: "r"(mb) : "memory")
__device__ __forceinline__ void bulk_g2s(uint32_t dst, const void* src, uint32_t bytes, uint32_t mb) {
    asm volatile(
        "cp.async.bulk.shared::cluster.global.mbarrier::complete_tx::bytes [%0], [%1], %2, [%3];"
        :: "r"(dst), "l"(src), "r"(bytes), "r"(mb) : "memory");
}
__device__ __forceinline__ void ldsm_x4(uint32_t& r0, uint32_t& r1, uint32_t& r2, uint32_t& r3,
                                        uint32_t addr) {
    asm volatile("ldmatrix.sync.aligned.m8n8.x4.shared.b16 {%0,%1,%2,%3}, [%4];"
                 : "=r"(r0), "=r"(r1), "=r"(r2), "=r"(r3) : "r"(addr));
}
__device__ __forceinline__ void mma_f16(float& c0, float& c1, float& c2, float& c3,
                                        uint32_t a0, uint32_t a1, uint32_t a2, uint32_t a3,
                                        uint32_t b0, uint32_t b1) {
    asm volatile(
        "mma.sync.aligned.m16n8k16.row.col.f32.f16.f16.f32 "
        "{%0,%1,%2,%3}, {%4,%5,%6,%7}, {%8,%9}, {%0,%1,%2,%3};"
        : "+f"(c0), "+f"(c1), "+f"(c2), "+f"(c3)
        : "r"(a0), "r"(a1), "r"(a2), "r"(a3), "r"(b0), "r"(b1));
}
// swizzled in-block byte offset for (row r, byte kb within 128B row)
__device__ __forceinline__ uint32_t swz(uint32_t r, uint32_t kb) {
    return r * 128u + (kb ^ ((r & 7u) << 4));
}

// ===================== Kernel 1: fused prep =====================
__global__ void kprep(const float* __restrict__ x, const float* __restrict__ feats,
                      const long long* __restrict__ ctgt) {
    int b = blockIdx.x;
    int t = threadIdx.x;  // 256

    if (b == 0 && t == 0) g_cnt = 0;   // reset reduce counter every launch

    if (b < NB_CONV) {
        // 16 elems/thread, two 16B stores (swizzle is 16B-granular)
        size_t e0 = ((size_t)b * 256 + t) * 16;
        #pragma unroll
        for (int j = 0; j < 2; j++) {
            size_t e = e0 + j * 8;
            float4 a  = *reinterpret_cast<const float4*>(feats + e);
            float4 a2 = *reinterpret_cast<const float4*>(feats + e + 4);
            uint4 o;
            o.x = h2u(__floats2half2_rn(a.x, a.y));
            o.y = h2u(__floats2half2_rn(a.z, a.w));
            o.z = h2u(__floats2half2_rn(a2.x, a2.y));
            o.w = h2u(__floats2half2_rn(a2.z, a2.w));
            uint32_t n = (uint32_t)(e >> 10), col = (uint32_t)(e & 1023);
            uint32_t blk = (n >> 7) * NKC + (col >> 6);
            uint32_t off = blk * BLKB + swz(n & 127u, (col & 63u) * 2u);
            *reinterpret_cast<uint4*>(reinterpret_cast<char*>(g_fh) + off) = o;
        }
        return;
    }

    if (b < NB_CONV + NB_NORM) {
        int row = b - NB_CONV;
        const float4* xr = reinterpret_cast<const float4*>(x + (size_t)row * DIM);
        float4 v = xr[t];
        float ss = v.x * v.x + v.y * v.y + v.z * v.z + v.w * v.w;
        #pragma unroll
        for (int o = 16; o; o >>= 1) ss += __shfl_xor_sync(~0u, ss, o);
        __shared__ float sw1[8];
        if ((t & 31) == 0) sw1[t >> 5] = ss;
        __syncthreads();
        float tot = sw1[0] + sw1[1] + sw1[2] + sw1[3] + sw1[4] + sw1[5] + sw1[6] + sw1[7];
        float sc = rsqrtf(fmaxf(tot, 1e-24f));
        uint2 o;
        o.x = h2u(__floats2half2_rn(v.x * sc, v.y * sc));
        o.y = h2u(__floats2half2_rn(v.z * sc, v.w * sc));
        uint32_t r = (uint32_t)(row & 127);
        uint32_t blk = (uint32_t)((row >> 7) * NKC + (t >> 4));
        uint32_t off = blk * BLKB + swz(r, (uint32_t)(t & 15) * 8u);
        *reinterpret_cast<uint2*>(reinterpret_cast<char*>(g_xh) + off) = o;
        return;
    }

    {   // target logit, fully fp32, computes its own norm
        int row = b - NB_CONV - NB_NORM;
        long long tg64 = ctgt[row];
        int tg = (int)(tg64 < 0 ? 0 : (tg64 >= NSAMP ? NSAMP - 1 : tg64));
        float4 a  = reinterpret_cast<const float4*>(x + (size_t)row * DIM)[t];
        float4 bb = reinterpret_cast<const float4*>(feats + (size_t)tg * DIM)[t];
        float s  = a.x * bb.x + a.y * bb.y + a.z * bb.z + a.w * bb.w;
        float ss = a.x * a.x + a.y * a.y + a.z * a.z + a.w * a.w;
        #pragma unroll
        for (int o = 16; o; o >>= 1) {
            s  += __shfl_xor_sync(~0u, s, o);
            ss += __shfl_xor_sync(~0u, ss, o);
        }
        __shared__ float sw2[16];
        if ((t & 31) == 0) { sw2[t >> 5] = s; sw2[8 + (t >> 5)] = ss; }
        __syncthreads();
        if (t == 0) {
            float ts = 0.f, tss = 0.f;
            #pragma unroll
            for (int i = 0; i < 8; i++) { ts += sw2[i]; tss += sw2[8 + i]; }
            g_tlogit[row] = ts * rsqrtf(fmaxf(tss, 1e-24f)) * TEMP_INV;
        }
    }
}

// ===================== Kernel 2: HMMA main, distributed producer ============
__global__ __launch_bounds__(128, 2)
void kmain() {
    extern __shared__ __align__(1024) char dyn[];
    __shared__ __align__(8) uint64_t s_mb[6];   // [0..2] data, [3..5] free

    const int t = threadIdx.x;                // 128 threads = 4 warps (2m x 2n)
    const int lane = t & 31, warp = t >> 5;
    const int wm = warp >> 1;
    const int wn = warp & 1;
    const int nti = blockIdx.y;

    const uint32_t base = smem_u32(dyn);
    const uint32_t mbd = smem_u32(&s_mb[0]);
    const uint32_t mbf = smem_u32(&s_mb[3]);

    const char* srcA = reinterpret_cast<const char*>(g_xh) + (size_t)blockIdx.x * NKC * BLKB;
    const char* srcB = reinterpret_cast<const char*>(g_fh) + (size_t)nti * NKC * BLKB;

    if (t == 0) {
        #pragma unroll
        for (int s = 0; s < 3; s++) { mbar_init(mbd + s * 8, 1); mbar_init(mbf + s * 8, 4); }
    }
    __syncthreads();

    // prologue: warps 0,1 issue chunks 0,1
    if (warp < 2 && lane == 0) {
        const int c = warp;
        MB_EXPECT(mbd + c * 8, STG);
        bulk_g2s(base + c * STG,        srcA + (size_t)c * BLKB, BLKB, mbd + c * 8);
        bulk_g2s(base + c * STG + BLKB, srcB + (size_t)c * BLKB, BLKB, mbd + c * 8);
    }

    const uint32_t a_r    = (uint32_t)(wm * 64 + (lane & 15));
    const uint32_t a_base = a_r * 128u;
    const uint32_t a_xor  = (a_r & 7u) << 4;
    const uint32_t a_cb   = (uint32_t)((lane >> 4) * 16);
    const uint32_t b_r    = (uint32_t)(wn * 64 + ((lane >> 4) * 8) + (lane & 7));
    const uint32_t b_base = b_r * 128u;
    const uint32_t b_xor  = (b_r & 7u) << 4;
    const uint32_t b_cb   = (uint32_t)(((lane >> 3) & 1) * 16);

    float c[4][8][4];
    #pragma unroll
    for (int i = 0; i < 4; i++)
        #pragma unroll
        for (int j = 0; j < 8; j++)
            #pragma unroll
            for (int q = 0; q < 4; q++) c[i][j][q] = 0.f;

    uint32_t a[2][4][4], b[2][4][4];

    // seed: wait chunk0, preload its ks0 frags into buf0
    mbar_wait(mbd, 0);
    {
        const uint32_t sA = base, sB = base + BLKB;
        #pragma unroll
        for (int mt = 0; mt < 4; mt++)
            ldsm_x4(a[0][mt][0], a[0][mt][1], a[0][mt][2], a[0][mt][3],
                    sA + a_base + mt * 2048u + (a_cb ^ a_xor));
        #pragma unroll
        for (int np = 0; np < 4; np++)
            ldsm_x4(b[0][np][0], b[0][np][1], b[0][np][2], b[0][np][3],
                    sB + b_base + np * 2048u + (b_cb ^ b_xor));
    }

    #pragma unroll 1
    for (int i = 0; i < NKC; i++) {
        const int s = i % 3;
        // distributed producer: warp sf refills buffer sf = (i+2)%3
        if (i + 2 < NKC) {
            const int sf = (i + 2) % 3;
            if (warp == sf && lane == 0) {
                if (i >= 1) mbar_wait(mbf + sf * 8, (uint32_t)(((i - 1) / 3) & 1));
                MB_EXPECT(mbd + sf * 8, STG);
                bulk_g2s(base + sf * STG,        srcA + (size_t)(i + 2) * BLKB, BLKB, mbd + sf * 8);
                bulk_g2s(base + sf * STG + BLKB, srcB + (size_t)(i + 2) * BLKB, BLKB, mbd + sf * 8);
            }
        }
        const uint32_t sA = base + (uint32_t)s * STG;
        const uint32_t sB = sA + BLKB;

        #pragma unroll
        for (int ks = 0; ks < 4; ks++) {
            const int cur = ks & 1, nxt = cur ^ 1;
            if (ks < 3) {
                const uint32_t kb = (uint32_t)((ks + 1) * 32);
                #pragma unroll
                for (int mt = 0; mt < 4; mt++)
                    ldsm_x4(a[nxt][mt][0], a[nxt][mt][1], a[nxt][mt][2], a[nxt][mt][3],
                            sA + a_base + mt * 2048u + ((kb + a_cb) ^ a_xor));
                #pragma unroll
                for (int np = 0; np < 4; np++)
                    ldsm_x4(b[nxt][np][0], b[nxt][np][1], b[nxt][np][2], b[nxt][np][3],
                            sB + b_base + np * 2048u + ((kb + b_cb) ^ b_xor));
                if (ks == 2 && lane == 0) MB_ARRIVE(mbf + s * 8);   // buffer s reads issued
            } else if (i + 1 < NKC) {
                const int sn = (i + 1) % 3;
                mbar_wait(mbd + sn * 8, (uint32_t)(((i + 1) / 3) & 1));
                const uint32_t nA = base + (uint32_t)sn * STG;
                const uint32_t nB = nA + BLKB;
                #pragma unroll
                for (int mt = 0; mt < 4; mt++)
                    ldsm_x4(a[nxt][mt][0], a[nxt][mt][1], a[nxt][mt][2], a[nxt][mt][3],
                            nA + a_base + mt * 2048u + (a_cb ^ a_xor));
                #pragma unroll
                for (int np = 0; np < 4; np++)
                    ldsm_x4(b[nxt][np][0], b[nxt][np][1], b[nxt][np][2], b[nxt][np][3],
                            nB + b_base + np * 2048u + (b_cb ^ b_xor));
            }
            #pragma unroll
            for (int mt = 0; mt < 4; mt++)
                #pragma unroll
                for (int np = 0; np < 4; np++) {
                    mma_f16(c[mt][2*np][0], c[mt][2*np][1], c[mt][2*np][2], c[mt][2*np][3],
                            a[cur][mt][0], a[cur][mt][1], a[cur][mt][2], a[cur][mt][3],
                            b[cur][np][0], b[cur][np][1]);
                    mma_f16(c[mt][2*np+1][0], c[mt][2*np+1][1], c[mt][2*np+1][2], c[mt][2*np+1][3],
                            a[cur][mt][0], a[cur][mt][1], a[cur][mt][2], a[cur][mt][3],
                            b[cur][np][2], b[cur][np][3]);
                }
        }
    }

    // ---- epilogue: exp-sum, shuffle-reduce, direct per-wn global write ----
    #pragma unroll
    for (int mt = 0; mt < 4; mt++)
        #pragma unroll
        for (int h = 0; h < 2; h++) {
            float rs = 0.f;
            #pragma unroll
            for (int ntl = 0; ntl < 8; ntl++)
                #pragma unroll
                for (int jc = 0; jc < 2; jc++) {
                    float v = c[mt][ntl][h * 2 + jc];
                    float e;
                    asm("ex2.approx.f32 %0, %1;" : "=f"(e) : "f"(v * EXP_SCALE));
                    rs += e;
                }
            rs += __shfl_xor_sync(~0u, rs, 1);
            rs += __shfl_xor_sync(~0u, rs, 2);
            if ((lane & 3) == 0) {
                int row = blockIdx.x * MT + wm * 64 + mt * 16 + (lane >> 2) + h * 8;
                g_partial[((size_t)row * NTILES + nti) * 2 + wn] = rs;
            }
        }
}

// ===================== Kernel 3: fused final reduce =====================
__global__ void kfin(float* __restrict__ out) {   // grid 32, block 256
    int bb = blockIdx.x, t = threadIdx.x, w = t >> 5, lane = t & 31;
    float acc = 0.f;
    for (int r0 = w; r0 < 128; r0 += 8) {
        int row = bb * 128 + r0;
        const float* p = g_partial + (size_t)row * NTILES * 2;
        float s = 0.f;
        #pragma unroll 4
        for (int i = lane; i < NTILES * 2; i += 32) s += p[i];
        #pragma unroll
        for (int o = 16; o; o >>= 1) s += __shfl_xor_sync(~0u, s, o);
        if (lane == 0) acc += logf(s) - g_tlogit[row];
    }
    __shared__ float sw[8];
    __shared__ int s_last;
    if (lane == 0) sw[w] = acc;
    __syncthreads();
    if (t == 0) {
        float v = 0.f;
        #pragma unroll
        for (int i = 0; i < 8; i++) v += sw[i];
        g_bsum[bb] = v;
        __threadfence();
        unsigned done = atomicAdd(&g_cnt, 1u);
        s_last = (done == 31u);
    }
    __syncthreads();
    if (s_last && t == 0) {
        float v = 0.f;
        #pragma unroll
        for (int i = 0; i < 32; i++) v += g_bsum[i];   // fixed order: deterministic
        out[0] = v * (1.0f / BATCH);
    }
}

// ===========================================================================
extern "C" void kernel_launch(void* const* d_in, const int* in_sizes, int n_in,
                              void* d_out, int out_size) {
    const float*     inputs = (const float*)d_in[0];
    const long long* ctgt   = (const long long*)d_in[2];
    const float*     feats  = (const float*)d_in[3];
    float* out = (float*)d_out;

    cudaFuncSetAttribute(kmain, cudaFuncAttributeMaxDynamicSharedMemorySize, SMEM_DYN);

    kprep<<<NB_CONV + NB_NORM + NB_TGT, 256>>>(inputs, feats, ctgt);
    dim3 grid(MTILES, NTILES);   // x = m (fast): CTAs sharing a B tile run together
    kmain<<<grid, 128, SMEM_DYN>>>();
    kfin<<<32, 256>>>(out);
}